// round 10
// baseline (speedup 1.0000x reference)
#include <cuda_runtime.h>
#include <math.h>
#include <stdint.h>

#define KB   2
#define KTQ  4096
#define KS   1024
#define KD   256
#define KH   8
#define KL   4
#define KP   2047
#define XE   (KB*KTQ*KD)

// pe | pp(x4) | kk(x4) | vv(x4) | qq | xx | ao | stats(float2 x 524288)
__device__ float g_scratch[12057344];

// ===================== mma.sync tf32 m16n8k8 helpers ========================
__device__ __forceinline__ void mma_tf32(float* c, const uint32_t* a, const uint32_t* b) {
    asm volatile("mma.sync.aligned.m16n8k8.row.col.f32.tf32.tf32.f32 "
        "{%0,%1,%2,%3}, {%4,%5,%6,%7}, {%8,%9}, {%0,%1,%2,%3};\n"
        : "+f"(c[0]), "+f"(c[1]), "+f"(c[2]), "+f"(c[3])
        : "r"(a[0]), "r"(a[1]), "r"(a[2]), "r"(a[3]), "r"(b[0]), "r"(b[1]));
}
__device__ __forceinline__ float cvt_tf32(float x) {
    float y;
    asm("cvt.rna.tf32.f32 %0, %1;" : "=f"(y) : "f"(x));
    return y;
}
__device__ __forceinline__ float4 cvt_tf32x4(float4 v) {
    v.x = cvt_tf32(v.x); v.y = cvt_tf32(v.y);
    v.z = cvt_tf32(v.z); v.w = cvt_tf32(v.w);
    return v;
}

// ============================ pe =================================
__global__ void pe_kernel(float* __restrict__ pe) {
    int i = blockIdx.x;
    int j = threadIdx.x;
    double div = exp(-(double)j * 9.210340371976184 / 128.0);
    double a = (1023.0 - (double)i) * div;
    pe[i * KD + 2 * j]     = (float)sin(a);
    pe[i * KD + 2 * j + 1] = (float)cos(a);
}

// ================= proj via 3xTF32 mma, 512 threads =========================
#define PJSTR 36
#define PJ_AB 0
#define PJ_AS 4608
#define PJ_WB 9216
#define PJ_WS 13824
#define PJ_SMEM (18432 * 4)

__global__ __launch_bounds__(512) void proj_mma(
    const float* __restrict__ A, const float* __restrict__ W,
    const float* __restrict__ bias, float* __restrict__ C,
    int M, int wStride, int cStride,
    const float* __restrict__ W2, const float* __restrict__ bias2,
    float* __restrict__ C2, int zSplit)
{
    extern __shared__ float sp[];
    int m0 = blockIdx.x * 128, n0 = blockIdx.y * 128;
    int z = blockIdx.z;
    if (z >= zSplit) { W = W2; bias = bias2; C = C2; z -= zSplit; }
    W += (long long)z * wStride;
    C += (long long)z * cStride;
    if (bias) bias += z * 256;
    int tid = threadIdx.x;
    int wid = tid >> 5, lane = tid & 31;
    int wy = wid >> 2, wx = wid & 3;
    int g = lane >> 2, t = lane & 3;
    float acc[2][4][4] = {};

    for (int k0 = 0; k0 < 256; k0 += 32) {
        #pragma unroll
        for (int it = 0; it < 2; it++) {
            int e = tid + 512 * it;
            int r = e >> 3, f = e & 7;
            int row = m0 + r;
            float4 a4 = (row < M) ? *(const float4*)&A[(long long)row * 256 + k0 + f * 4]
                                  : make_float4(0.f, 0.f, 0.f, 0.f);
            float4 ab = cvt_tf32x4(a4);
            float4 as = make_float4(a4.x - ab.x, a4.y - ab.y, a4.z - ab.z, a4.w - ab.w);
            *(float4*)&sp[PJ_AB + r * PJSTR + f * 4] = ab;
            *(float4*)&sp[PJ_AS + r * PJSTR + f * 4] = cvt_tf32x4(as);
            float4 w4 = *(const float4*)&W[(long long)(n0 + r) * 256 + k0 + f * 4];
            float4 wb = cvt_tf32x4(w4);
            float4 ws4 = make_float4(w4.x - wb.x, w4.y - wb.y, w4.z - wb.z, w4.w - wb.w);
            *(float4*)&sp[PJ_WB + r * PJSTR + f * 4] = wb;
            *(float4*)&sp[PJ_WS + r * PJSTR + f * 4] = cvt_tf32x4(ws4);
        }
        __syncthreads();
        #pragma unroll
        for (int k0i = 0; k0i < 4; k0i++) {
            int kk = k0i * 8;
            uint32_t aB[2][4], aS[2][4], bB[4][2], bS[4][2];
            #pragma unroll
            for (int mi = 0; mi < 2; mi++) {
                int r0 = wy * 32 + mi * 16;
                aB[mi][0] = __float_as_uint(sp[PJ_AB + (r0 + g) * PJSTR + kk + t]);
                aB[mi][1] = __float_as_uint(sp[PJ_AB + (r0 + g + 8) * PJSTR + kk + t]);
                aB[mi][2] = __float_as_uint(sp[PJ_AB + (r0 + g) * PJSTR + kk + t + 4]);
                aB[mi][3] = __float_as_uint(sp[PJ_AB + (r0 + g + 8) * PJSTR + kk + t + 4]);
                aS[mi][0] = __float_as_uint(sp[PJ_AS + (r0 + g) * PJSTR + kk + t]);
                aS[mi][1] = __float_as_uint(sp[PJ_AS + (r0 + g + 8) * PJSTR + kk + t]);
                aS[mi][2] = __float_as_uint(sp[PJ_AS + (r0 + g) * PJSTR + kk + t + 4]);
                aS[mi][3] = __float_as_uint(sp[PJ_AS + (r0 + g + 8) * PJSTR + kk + t + 4]);
            }
            #pragma unroll
            for (int ni = 0; ni < 4; ni++) {
                int c0 = wx * 32 + ni * 8;
                bB[ni][0] = __float_as_uint(sp[PJ_WB + (c0 + g) * PJSTR + kk + t]);
                bB[ni][1] = __float_as_uint(sp[PJ_WB + (c0 + g) * PJSTR + kk + t + 4]);
                bS[ni][0] = __float_as_uint(sp[PJ_WS + (c0 + g) * PJSTR + kk + t]);
                bS[ni][1] = __float_as_uint(sp[PJ_WS + (c0 + g) * PJSTR + kk + t + 4]);
            }
            #pragma unroll
            for (int mi = 0; mi < 2; mi++)
                #pragma unroll
                for (int ni = 0; ni < 4; ni++) {
                    mma_tf32(acc[mi][ni], aB[mi], bS[ni]);
                    mma_tf32(acc[mi][ni], aS[mi], bB[ni]);
                    mma_tf32(acc[mi][ni], aB[mi], bB[ni]);
                }
        }
        __syncthreads();
    }
    #pragma unroll
    for (int mi = 0; mi < 2; mi++) {
        int r1 = m0 + wy * 32 + mi * 16 + g;
        int r2 = r1 + 8;
        #pragma unroll
        for (int ni = 0; ni < 4; ni++) {
            int cx = wx * 32 + ni * 8 + 2 * t;
            float b0 = bias ? bias[n0 + cx] : 0.f;
            float b1 = bias ? bias[n0 + cx + 1] : 0.f;
            if (r1 < M)
                *(float2*)&C[(long long)r1 * 256 + n0 + cx] =
                    make_float2(acc[mi][ni][0] + b0, acc[mi][ni][1] + b1);
            if (r2 < M)
                *(float2*)&C[(long long)r2 * 256 + n0 + cx] =
                    make_float2(acc[mi][ni][2] + b0, acc[mi][ni][3] + b1);
        }
    }
}

// ====================== scores: q-tile 64, 2 CTAs/SM ========================
// score = (Q.K + buK[c] + G[r][ix] + bvP[ix]) / sqrt(32),  ix = c - r + 63
// G[r][ix] = Q_shifted[r] . Pd[ix]  (banded MMA; SIMT fallback on boundary)
#define PSTR 36
#define Q_O  0
#define KT_O 2412
#define PD_O 7020
#define G_O  13932
#define GSTR 196
#define BK_O 26476
#define BP_O 26604
#define SX_O 26796
#define SS_O 27052
#define BU_O 27308
#define BV_O 27340
#define SC_FLOATS 27372
#define SC_SMEM (SC_FLOATS * 4)

__global__ __launch_bounds__(256, 2) void scores_mma_kernel(
    const float* __restrict__ q, const float* __restrict__ kmat,
    const float* __restrict__ p, const float* __restrict__ pbu,
    const float* __restrict__ pbv, float* __restrict__ ws,
    float2* __restrict__ gstats)
{
    extern __shared__ float sm[];
    int q0 = blockIdx.x * 64, m0 = blockIdx.y * 128;
    int bh = blockIdx.z;
    int b = bh >> 3, h = bh & 7;
    int tid = threadIdx.x;
    int wid = tid >> 5, lane = tid & 31;
    int wy = wid >> 2, wx = wid & 3;        // 2x4 warp grid
    int g = lane >> 2, t = lane & 3;

    int dlo = m0 - q0 + 4033;               // m0 - (q0+63) + 4096
    int da  = dlo >> 11;
    bool boundary = (da != ((dlo + 190) >> 11));

    const float* qb = q + (long long)b * KTQ * 256 + h * 32;
    // stage Q rows [q0, q0+67) unbiased
    for (int e = tid; e < 67 * 8; e += 256) {
        int r = e >> 3, fj = e & 7;
        int rv = q0 + r; if (rv > KTQ - 1) rv = KTQ - 1;
        float4 a = *(const float4*)&qb[(long long)rv * 256 + fj * 4];
        *(float4*)&sm[Q_O + r * PSTR + fj * 4] = cvt_tf32x4(a);
    }
    // stage K tile
    #pragma unroll
    for (int it = 0; it < 4; it++) {
        int e = tid + 256 * it;
        int r = e >> 3, fj = e & 7;
        float4 kk4 = *(const float4*)&kmat[(long long)(m0 + r) * 256 + h * 32 + fj * 4];
        *(float4*)&sm[KT_O + r * PSTR + fj * 4] = cvt_tf32x4(kk4);
    }
    // stage Pd window (192 rows; zero where invalid)
    #pragma unroll
    for (int it = 0; it < 6; it++) {
        int e = tid + 256 * it;
        int r = e >> 3, fj = e & 7;
        int d = dlo + r;
        int cm = d & 2047;
        float4 v = make_float4(0.f, 0.f, 0.f, 0.f);
        if (cm > 0 && r < 191)
            v = cvt_tf32x4(*(const float4*)&p[(long long)(cm - 1) * 256 + h * 32 + fj * 4]);
        *(float4*)&sm[PD_O + r * PSTR + fj * 4] = v;
    }
    if (tid < 32) sm[BU_O + tid] = pbu[h * 32 + tid];
    else if (tid < 64) sm[BV_O + tid - 32] = pbv[h * 32 + tid - 32];
    __syncthreads();

    // bias-dot vectors: buK[c] = bu.K[c], bvP[ix] = bv.Pd[ix]
    if (tid < 128) {
        float s = 0.f;
        #pragma unroll
        for (int k = 0; k < 32; k++) s += sm[BU_O + k] * sm[KT_O + tid * PSTR + k];
        sm[BK_O + tid] = s;
    } else {
        for (int j = tid - 128; j < 192; j += 128) {
            float s = 0.f;
            #pragma unroll
            for (int k = 0; k < 32; k++) s += sm[BV_O + k] * sm[PD_O + j * PSTR + k];
            sm[BP_O + j] = s;
        }
    }

    // ---- phase 1: banded G (no barrier needed before: G area untouched) ----
    if (!boundary) {
        int s0b = 32 * (1 - wy);            // band ix-window start, width 160
        float accg[2][5][4] = {};
        #pragma unroll
        for (int k0 = 0; k0 < 4; k0++) {
            int kk = k0 * 8;
            uint32_t a[2][4], bb[5][2];
            #pragma unroll
            for (int mi = 0; mi < 2; mi++) {
                int r0 = wy * 32 + mi * 16 + da;
                a[mi][0] = __float_as_uint(sm[Q_O + (r0 + g) * PSTR + kk + t]);
                a[mi][1] = __float_as_uint(sm[Q_O + (r0 + g + 8) * PSTR + kk + t]);
                a[mi][2] = __float_as_uint(sm[Q_O + (r0 + g) * PSTR + kk + t + 4]);
                a[mi][3] = __float_as_uint(sm[Q_O + (r0 + g + 8) * PSTR + kk + t + 4]);
            }
            #pragma unroll
            for (int ni = 0; ni < 5; ni++) {
                int c0 = s0b + (wx * 5 + ni) * 8;
                bb[ni][0] = __float_as_uint(sm[PD_O + (c0 + g) * PSTR + kk + t]);
                bb[ni][1] = __float_as_uint(sm[PD_O + (c0 + g) * PSTR + kk + t + 4]);
            }
            #pragma unroll
            for (int mi = 0; mi < 2; mi++)
                #pragma unroll
                for (int ni = 0; ni < 5; ni++)
                    mma_tf32(accg[mi][ni], a[mi], bb[ni]);
        }
        #pragma unroll
        for (int mi = 0; mi < 2; mi++) {
            int r1 = wy * 32 + mi * 16 + g;
            #pragma unroll
            for (int ni = 0; ni < 5; ni++) {
                int cx = s0b + (wx * 5 + ni) * 8 + 2 * t;
                *(float2*)&sm[G_O + r1 * GSTR + cx] =
                    make_float2(accg[mi][ni][0], accg[mi][ni][1]);
                *(float2*)&sm[G_O + (r1 + 8) * GSTR + cx] =
                    make_float2(accg[mi][ni][2], accg[mi][ni][3]);
            }
        }
    } else {
        int trb = (tid >> 4) * 4, tcb = (tid & 15) * 8;
        #pragma unroll
        for (int i = 0; i < 4; i++) {
            int rr = trb + i;
            #pragma unroll
            for (int j = 0; j < 8; j++) {
                int c = tcb + j;
                int ix = c - rr + 63;
                int d = dlo + ix;
                int tt = rr + (d >> 11);
                float s = 0.f;
                #pragma unroll
                for (int k = 0; k < 32; k++)
                    s += sm[Q_O + tt * PSTR + k] * sm[PD_O + ix * PSTR + k];
                sm[G_O + rr * GSTR + ix] = s;
            }
        }
    }
    __syncthreads();

    // ---- phase 2: ac = Q . K^T ----
    float acc[2][4][4] = {};
    #pragma unroll
    for (int k0 = 0; k0 < 4; k0++) {
        int kk = k0 * 8;
        uint32_t a[2][4], bb[4][2];
        #pragma unroll
        for (int mi = 0; mi < 2; mi++) {
            int r0 = wy * 32 + mi * 16;
            a[mi][0] = __float_as_uint(sm[Q_O + (r0 + g) * PSTR + kk + t]);
            a[mi][1] = __float_as_uint(sm[Q_O + (r0 + g + 8) * PSTR + kk + t]);
            a[mi][2] = __float_as_uint(sm[Q_O + (r0 + g) * PSTR + kk + t + 4]);
            a[mi][3] = __float_as_uint(sm[Q_O + (r0 + g + 8) * PSTR + kk + t + 4]);
        }
        #pragma unroll
        for (int ni = 0; ni < 4; ni++) {
            int c0 = wx * 32 + ni * 8;
            bb[ni][0] = __float_as_uint(sm[KT_O + (c0 + g) * PSTR + kk + t]);
            bb[ni][1] = __float_as_uint(sm[KT_O + (c0 + g) * PSTR + kk + t + 4]);
        }
        #pragma unroll
        for (int mi = 0; mi < 2; mi++)
            #pragma unroll
            for (int ni = 0; ni < 4; ni++)
                mma_tf32(acc[mi][ni], a[mi], bb[ni]);
    }

    // ---- combine + store raw scores ----
    const float sc = 0.17677669529663687f;
    #pragma unroll
    for (int mi = 0; mi < 2; mi++) {
        int r1 = wy * 32 + mi * 16 + g;
        int r2 = r1 + 8;
        long long grow1 = ((long long)bh * KTQ + q0 + r1) * KS + m0;
        long long grow2 = grow1 + 8 * KS;
        #pragma unroll
        for (int ni = 0; ni < 4; ni++) {
            int cx = wx * 32 + ni * 8 + 2 * t;
            int ix10 = cx - r1 + 63, ix20 = cx - r2 + 63;
            acc[mi][ni][0] = (acc[mi][ni][0] + sm[BK_O + cx]
                              + sm[G_O + r1 * GSTR + ix10] + sm[BP_O + ix10]) * sc;
            acc[mi][ni][1] = (acc[mi][ni][1] + sm[BK_O + cx + 1]
                              + sm[G_O + r1 * GSTR + ix10 + 1] + sm[BP_O + ix10 + 1]) * sc;
            acc[mi][ni][2] = (acc[mi][ni][2] + sm[BK_O + cx]
                              + sm[G_O + r2 * GSTR + ix20] + sm[BP_O + ix20]) * sc;
            acc[mi][ni][3] = (acc[mi][ni][3] + sm[BK_O + cx + 1]
                              + sm[G_O + r2 * GSTR + ix20 + 1] + sm[BP_O + ix20 + 1]) * sc;
            *(float2*)&ws[grow1 + cx] = make_float2(acc[mi][ni][0], acc[mi][ni][1]);
            *(float2*)&ws[grow2 + cx] = make_float2(acc[mi][ni][2], acc[mi][ni][3]);
        }
    }

    // ---- softmax tile stats ----
    __syncthreads();
    float rm1[2], rm2[2];
    #pragma unroll
    for (int mi = 0; mi < 2; mi++) {
        int lr1 = wy * 32 + mi * 16 + g;
        int lr2 = lr1 + 8;
        float mx1 = -1e30f, mx2 = -1e30f;
        #pragma unroll
        for (int ni = 0; ni < 4; ni++) {
            mx1 = fmaxf(mx1, fmaxf(acc[mi][ni][0], acc[mi][ni][1]));
            mx2 = fmaxf(mx2, fmaxf(acc[mi][ni][2], acc[mi][ni][3]));
        }
        mx1 = fmaxf(mx1, __shfl_xor_sync(0xffffffffu, mx1, 1));
        mx1 = fmaxf(mx1, __shfl_xor_sync(0xffffffffu, mx1, 2));
        mx2 = fmaxf(mx2, __shfl_xor_sync(0xffffffffu, mx2, 1));
        mx2 = fmaxf(mx2, __shfl_xor_sync(0xffffffffu, mx2, 2));
        if (t == 0) {
            sm[SX_O + lr1 * 4 + wx] = mx1;
            sm[SX_O + lr2 * 4 + wx] = mx2;
        }
    }
    __syncthreads();
    #pragma unroll
    for (int mi = 0; mi < 2; mi++) {
        int lr1 = wy * 32 + mi * 16 + g;
        int lr2 = lr1 + 8;
        float a1 = fmaxf(fmaxf(sm[SX_O + lr1 * 4], sm[SX_O + lr1 * 4 + 1]),
                         fmaxf(sm[SX_O + lr1 * 4 + 2], sm[SX_O + lr1 * 4 + 3]));
        float a2 = fmaxf(fmaxf(sm[SX_O + lr2 * 4], sm[SX_O + lr2 * 4 + 1]),
                         fmaxf(sm[SX_O + lr2 * 4 + 2], sm[SX_O + lr2 * 4 + 3]));
        rm1[mi] = a1; rm2[mi] = a2;
        float s1 = 0.f, s2 = 0.f;
        #pragma unroll
        for (int ni = 0; ni < 4; ni++) {
            s1 += __expf(acc[mi][ni][0] - a1) + __expf(acc[mi][ni][1] - a1);
            s2 += __expf(acc[mi][ni][2] - a2) + __expf(acc[mi][ni][3] - a2);
        }
        s1 += __shfl_xor_sync(0xffffffffu, s1, 1);
        s1 += __shfl_xor_sync(0xffffffffu, s1, 2);
        s2 += __shfl_xor_sync(0xffffffffu, s2, 1);
        s2 += __shfl_xor_sync(0xffffffffu, s2, 2);
        if (t == 0) {
            sm[SS_O + lr1 * 4 + wx] = s1;
            sm[SS_O + lr2 * 4 + wx] = s2;
        }
    }
    __syncthreads();
    if (wx == 0 && t == 0) {
        int my = m0 >> 7;
        long long sb = ((long long)bh * 8 + my) * KTQ + q0;
        #pragma unroll
        for (int mi = 0; mi < 2; mi++) {
            int lr1 = wy * 32 + mi * 16 + g;
            int lr2 = lr1 + 8;
            float s1 = sm[SS_O + lr1 * 4] + sm[SS_O + lr1 * 4 + 1]
                     + sm[SS_O + lr1 * 4 + 2] + sm[SS_O + lr1 * 4 + 3];
            float s2 = sm[SS_O + lr2 * 4] + sm[SS_O + lr2 * 4 + 1]
                     + sm[SS_O + lr2 * 4 + 2] + sm[SS_O + lr2 * 4 + 3];
            gstats[sb + lr1] = make_float2(rm1[mi], s1);
            gstats[sb + lr2] = make_float2(rm2[mi], s2);
        }
    }
}

// =============== av fused: softmax-normalize + attn@V ======================
#define AVSTR 68
#define AV_A 0
#define AV_V 8704
#define AV_M 10880
#define AV_I 11008
#define AV_S 11136
#define AV_SMEM (13184 * 4)

__global__ __launch_bounds__(256) void av_fused(
    float* __restrict__ ws, const float* __restrict__ vmat,
    const float2* __restrict__ gstats, float* __restrict__ ao)
{
    extern __shared__ float sv[];
    float2* sSt = (float2*)(sv + AV_S);
    int q0 = blockIdx.x * 128;
    int bh = blockIdx.y;
    int b = bh >> 3, h = bh & 7;
    int tid = threadIdx.x;
    int wid = tid >> 5, lane = tid & 31;
    int g = lane >> 2, t = lane & 3;

    for (int idx = tid; idx < 1024; idx += 256)
        sSt[idx] = gstats[(((long long)bh * 8 + (idx >> 7)) << 12) + q0 + (idx & 127)];
    __syncthreads();
    if (tid < 128) {
        float M = -1e30f;
        #pragma unroll
        for (int mt = 0; mt < 8; mt++) M = fmaxf(M, sSt[mt * 128 + tid].x);
        float s = 0.f;
        #pragma unroll
        for (int mt = 0; mt < 8; mt++)
            s += sSt[mt * 128 + tid].y * __expf(sSt[mt * 128 + tid].x - M);
        sv[AV_M + tid] = M;
        sv[AV_I + tid] = 1.f / s;
    }
    __syncthreads();

    float* wsrow = ws + ((long long)bh * KTQ + q0) * KS;
    float acc[4][4] = {};

    for (int s0 = 0; s0 < KS; s0 += 64) {
        #pragma unroll
        for (int it = 0; it < 8; it++) {
            int e = tid + 256 * it;
            int r = e >> 4, f = e & 15;
            float4 raw = *(float4*)&wsrow[(long long)r * KS + s0 + f * 4];
            float m = sv[AV_M + r], inv = sv[AV_I + r];
            float4 pp;
            pp.x = __expf(raw.x - m) * inv;
            pp.y = __expf(raw.y - m) * inv;
            pp.z = __expf(raw.z - m) * inv;
            pp.w = __expf(raw.w - m) * inv;
            *(float4*)&wsrow[(long long)r * KS + s0 + f * 4] = pp;
            *(float4*)&sv[AV_A + r * AVSTR + f * 4] = cvt_tf32x4(pp);
        }
        #pragma unroll
        for (int it = 0; it < 8; it++) {
            int e = tid + 256 * it;
            int k = e >> 5, n = e & 31;
            sv[AV_V + n * AVSTR + k] =
                cvt_tf32(vmat[(long long)(s0 + k) * 256 + h * 32 + n]);
        }
        __syncthreads();
        int r0 = wid * 16;
        #pragma unroll
        for (int k0 = 0; k0 < 8; k0++) {
            int kk = k0 * 8;
            uint32_t a[4];
            a[0] = __float_as_uint(sv[AV_A + (r0 + g) * AVSTR + kk + t]);
            a[1] = __float_as_uint(sv[AV_A + (r0 + g + 8) * AVSTR + kk + t]);
            a[2] = __float_as_uint(sv[AV_A + (r0 + g) * AVSTR + kk + t + 4]);
            a[3] = __float_as_uint(sv[AV_A + (r0 + g + 8) * AVSTR + kk + t + 4]);
            #pragma unroll
            for (int ni = 0; ni < 4; ni++) {
                uint32_t bb[2];
                bb[0] = __float_as_uint(sv[AV_V + (ni * 8 + g) * AVSTR + kk + t]);
                bb[1] = __float_as_uint(sv[AV_V + (ni * 8 + g) * AVSTR + kk + t + 4]);
                mma_tf32(acc[ni], a, bb);
            }
        }
        __syncthreads();
    }
    int r1 = q0 + wid * 16 + g;
    float* aob = ao + ((long long)b * KTQ + r1) * 256 + h * 32;
    #pragma unroll
    for (int ni = 0; ni < 4; ni++) {
        int cx = ni * 8 + 2 * t;
        *(float2*)&aob[cx]           = make_float2(acc[ni][0], acc[ni][1]);
        *(float2*)&aob[8 * 256 + cx] = make_float2(acc[ni][2], acc[ni][3]);
    }
}

// ---------------------------------------------------------------------------
extern "C" void kernel_launch(void* const* d_in, const int* in_sizes, int n_in,
                              void* d_out, int out_size)
{
    const float* vis  = (const float*)d_in[0];
    const float* mem  = (const float*)d_in[1];
    const float* Wq   = (const float*)d_in[3];
    const float* bq   = (const float*)d_in[4];
    const float* Wk   = (const float*)d_in[5];
    const float* bk   = (const float*)d_in[6];
    const float* Wv   = (const float*)d_in[7];
    const float* bv   = (const float*)d_in[8];
    const float* Wo   = (const float*)d_in[9];
    const float* bo   = (const float*)d_in[10];
    const float* Wpos = (const float*)d_in[11];
    const float* pbu  = (const float*)d_in[12];
    const float* pbv  = (const float*)d_in[13];

    float* out    = (float*)d_out;
    float* out_ws = out + XE;

    float* scratch = nullptr;
    cudaGetSymbolAddress((void**)&scratch, g_scratch);
    float* pe = scratch;
    float* pp = pe + 524032;
    float* kk = pp + 4 * 524032;
    float* vv = kk + 4 * 262144;
    float* qq = vv + 4 * 262144;
    float* xx = qq + XE;
    float* ao = xx + XE;
    float2* gstats = (float2*)(ao + XE);

    cudaFuncSetAttribute(scores_mma_kernel,
        cudaFuncAttributeMaxDynamicSharedMemorySize, SC_SMEM);
    cudaFuncSetAttribute(proj_mma,
        cudaFuncAttributeMaxDynamicSharedMemorySize, PJ_SMEM);
    cudaFuncSetAttribute(av_fused,
        cudaFuncAttributeMaxDynamicSharedMemorySize, AV_SMEM);

    pe_kernel<<<KP, 128>>>(pe);

    proj_mma<<<dim3(8, 2, 2 * KL), 512, PJ_SMEM>>>(mem, Wk, bk, kk, KS, 65536, 262144,
                                                   Wv, bv, vv, KL);
    proj_mma<<<dim3(16, 2, KL), 512, PJ_SMEM>>>(pe, Wpos, nullptr, pp, KP, 65536, 524032,
                                                nullptr, nullptr, nullptr, 1 << 30);

    const float* cur = vis;
    for (int l = 0; l < KL; l++) {
        proj_mma<<<dim3(64, 2, 1), 512, PJ_SMEM>>>(cur, Wq + l * 65536, bq + l * 256,
                                                   qq, KB * KTQ, 0, 0,
                                                   nullptr, nullptr, nullptr, 1 << 30);
        float* wsl = out_ws + (long long)l * KB * KH * KTQ * KS;
        scores_mma_kernel<<<dim3(64, 8, 16), 256, SC_SMEM>>>(
            qq, kk + l * 262144, pp + l * 524032,
            pbu + l * 256, pbv + l * 256, wsl, gstats);
        av_fused<<<dim3(32, 16), 256, AV_SMEM>>>(wsl, vv + l * 262144, gstats, ao);
        float* nxt = (l == KL - 1) ? out : xx;
        proj_mma<<<dim3(64, 2, 1), 512, PJ_SMEM>>>(ao, Wo + l * 65536, bo + l * 256,
                                                   nxt, KB * KTQ, 0, 0,
                                                   nullptr, nullptr, nullptr, 1 << 30);
        cur = nxt;
    }
}

// round 11
// speedup vs baseline: 1.1632x; 1.1632x over previous
#include <cuda_runtime.h>
#include <math.h>
#include <stdint.h>

#define KB   2
#define KTQ  4096
#define KS   1024
#define KD   256
#define KH   8
#define KL   4
#define KP   2047
#define XE   (KB*KTQ*KD)

// pe | pp(x4) | kk(x4) | vv(x4) | qq | xx | ao | stats(float2 x 524288)
__device__ float g_scratch[12057344];

// ===================== mma.sync tf32 m16n8k8 helpers ========================
__device__ __forceinline__ void mma_tf32(float* c, const uint32_t* a, const uint32_t* b) {
    asm volatile("mma.sync.aligned.m16n8k8.row.col.f32.tf32.tf32.f32 "
        "{%0,%1,%2,%3}, {%4,%5,%6,%7}, {%8,%9}, {%0,%1,%2,%3};\n"
        : "+f"(c[0]), "+f"(c[1]), "+f"(c[2]), "+f"(c[3])
        : "r"(a[0]), "r"(a[1]), "r"(a[2]), "r"(a[3]), "r"(b[0]), "r"(b[1]));
}
__device__ __forceinline__ float cvt_tf32(float x) {
    float y;
    asm("cvt.rna.tf32.f32 %0, %1;" : "=f"(y) : "f"(x));
    return y;
}
__device__ __forceinline__ float4 cvt_tf32x4(float4 v) {
    v.x = cvt_tf32(v.x); v.y = cvt_tf32(v.y);
    v.z = cvt_tf32(v.z); v.w = cvt_tf32(v.w);
    return v;
}

// ============================ pe =================================
__global__ void pe_kernel(float* __restrict__ pe) {
    int i = blockIdx.x;
    int j = threadIdx.x;
    double div = exp(-(double)j * 9.210340371976184 / 128.0);
    double a = (1023.0 - (double)i) * div;
    pe[i * KD + 2 * j]     = (float)sin(a);
    pe[i * KD + 2 * j + 1] = (float)cos(a);
}

// ================= proj via 3xTF32 mma, 512 threads =========================
#define PJSTR 36
#define PJ_AB 0
#define PJ_AS 4608
#define PJ_WB 9216
#define PJ_WS 13824
#define PJ_SMEM (18432 * 4)

__global__ __launch_bounds__(512) void proj_mma(
    const float* __restrict__ A, const float* __restrict__ W,
    const float* __restrict__ bias, float* __restrict__ C,
    int M, int wStride, int cStride,
    const float* __restrict__ W2, const float* __restrict__ bias2,
    float* __restrict__ C2, int zSplit)
{
    extern __shared__ float sp[];
    int m0 = blockIdx.x * 128, n0 = blockIdx.y * 128;
    int z = blockIdx.z;
    if (z >= zSplit) { W = W2; bias = bias2; C = C2; z -= zSplit; }
    W += (long long)z * wStride;
    C += (long long)z * cStride;
    if (bias) bias += z * 256;
    int tid = threadIdx.x;
    int wid = tid >> 5, lane = tid & 31;
    int wy = wid >> 2, wx = wid & 3;
    int g = lane >> 2, t = lane & 3;
    float acc[2][4][4] = {};

    for (int k0 = 0; k0 < 256; k0 += 32) {
        #pragma unroll
        for (int it = 0; it < 2; it++) {
            int e = tid + 512 * it;
            int r = e >> 3, f = e & 7;
            int row = m0 + r;
            float4 a4 = (row < M) ? *(const float4*)&A[(long long)row * 256 + k0 + f * 4]
                                  : make_float4(0.f, 0.f, 0.f, 0.f);
            float4 ab = cvt_tf32x4(a4);
            float4 as = make_float4(a4.x - ab.x, a4.y - ab.y, a4.z - ab.z, a4.w - ab.w);
            *(float4*)&sp[PJ_AB + r * PJSTR + f * 4] = ab;
            *(float4*)&sp[PJ_AS + r * PJSTR + f * 4] = cvt_tf32x4(as);
            float4 w4 = *(const float4*)&W[(long long)(n0 + r) * 256 + k0 + f * 4];
            float4 wb = cvt_tf32x4(w4);
            float4 ws4 = make_float4(w4.x - wb.x, w4.y - wb.y, w4.z - wb.z, w4.w - wb.w);
            *(float4*)&sp[PJ_WB + r * PJSTR + f * 4] = wb;
            *(float4*)&sp[PJ_WS + r * PJSTR + f * 4] = cvt_tf32x4(ws4);
        }
        __syncthreads();
        #pragma unroll
        for (int k0i = 0; k0i < 4; k0i++) {
            int kk = k0i * 8;
            uint32_t aB[2][4], aS[2][4], bB[4][2], bS[4][2];
            #pragma unroll
            for (int mi = 0; mi < 2; mi++) {
                int r0 = wy * 32 + mi * 16;
                aB[mi][0] = __float_as_uint(sp[PJ_AB + (r0 + g) * PJSTR + kk + t]);
                aB[mi][1] = __float_as_uint(sp[PJ_AB + (r0 + g + 8) * PJSTR + kk + t]);
                aB[mi][2] = __float_as_uint(sp[PJ_AB + (r0 + g) * PJSTR + kk + t + 4]);
                aB[mi][3] = __float_as_uint(sp[PJ_AB + (r0 + g + 8) * PJSTR + kk + t + 4]);
                aS[mi][0] = __float_as_uint(sp[PJ_AS + (r0 + g) * PJSTR + kk + t]);
                aS[mi][1] = __float_as_uint(sp[PJ_AS + (r0 + g + 8) * PJSTR + kk + t]);
                aS[mi][2] = __float_as_uint(sp[PJ_AS + (r0 + g) * PJSTR + kk + t + 4]);
                aS[mi][3] = __float_as_uint(sp[PJ_AS + (r0 + g + 8) * PJSTR + kk + t + 4]);
            }
            #pragma unroll
            for (int ni = 0; ni < 4; ni++) {
                int c0 = wx * 32 + ni * 8;
                bB[ni][0] = __float_as_uint(sp[PJ_WB + (c0 + g) * PJSTR + kk + t]);
                bB[ni][1] = __float_as_uint(sp[PJ_WB + (c0 + g) * PJSTR + kk + t + 4]);
                bS[ni][0] = __float_as_uint(sp[PJ_WS + (c0 + g) * PJSTR + kk + t]);
                bS[ni][1] = __float_as_uint(sp[PJ_WS + (c0 + g) * PJSTR + kk + t + 4]);
            }
            #pragma unroll
            for (int mi = 0; mi < 2; mi++)
                #pragma unroll
                for (int ni = 0; ni < 4; ni++) {
                    mma_tf32(acc[mi][ni], aB[mi], bS[ni]);
                    mma_tf32(acc[mi][ni], aS[mi], bB[ni]);
                    mma_tf32(acc[mi][ni], aB[mi], bB[ni]);
                }
        }
        __syncthreads();
    }
    #pragma unroll
    for (int mi = 0; mi < 2; mi++) {
        int r1 = m0 + wy * 32 + mi * 16 + g;
        int r2 = r1 + 8;
        #pragma unroll
        for (int ni = 0; ni < 4; ni++) {
            int cx = wx * 32 + ni * 8 + 2 * t;
            float b0 = bias ? bias[n0 + cx] : 0.f;
            float b1 = bias ? bias[n0 + cx + 1] : 0.f;
            if (r1 < M)
                *(float2*)&C[(long long)r1 * 256 + n0 + cx] =
                    make_float2(acc[mi][ni][0] + b0, acc[mi][ni][1] + b1);
            if (r2 < M)
                *(float2*)&C[(long long)r2 * 256 + n0 + cx] =
                    make_float2(acc[mi][ni][2] + b0, acc[mi][ni][3] + b1);
        }
    }
}

// ====================== scores via mma.sync tf32, 256 threads ===============
// Banded G phase (R9). Epilogue stores exp(v - tile_max) into ws instead of
// raw v; av then normalizes with one multiply per element.
#define PSTR 36
#define QU_O 0
#define KT_O 4608
#define QV_O 9216
#define PD_O 13860
#define G_O  23076
#define GSTR 260
#define SMAX_O (G_O + 128 * GSTR)
#define SSUM_O (SMAX_O + 512)
#define SC_FLOATS (SSUM_O + 512)
#define SC_SMEM (SC_FLOATS * 4)

__global__ __launch_bounds__(256, 1) void scores_mma_kernel(
    const float* __restrict__ q, const float* __restrict__ kmat,
    const float* __restrict__ p, const float* __restrict__ pbu,
    const float* __restrict__ pbv, float* __restrict__ ws,
    float2* __restrict__ gstats)
{
    extern __shared__ float sm[];
    int q0 = blockIdx.x * 128, m0 = blockIdx.y * 128;
    int bh = blockIdx.z;
    int b = bh >> 3, h = bh & 7;
    int tid = threadIdx.x;
    int wid = tid >> 5, lane = tid & 31;
    int wy = wid >> 2, wx = wid & 3;        // 2x4 warp grid
    int g = lane >> 2, t = lane & 3;

    int dlo = m0 - q0 + 3969;
    int da  = dlo >> 11;
    bool boundary = ((dlo >> 11) != ((dlo + 254) >> 11));

    const float* qb = q + (long long)b * KTQ * 256 + h * 32;
    #pragma unroll
    for (int it = 0; it < 4; it++) {
        int e = tid + 256 * it;
        int r = e >> 3, fj = e & 7;
        float4 bu4 = *(const float4*)&pbu[h * 32 + fj * 4];
        float4 a = *(const float4*)&qb[(long long)(q0 + r) * 256 + fj * 4];
        a.x += bu4.x; a.y += bu4.y; a.z += bu4.z; a.w += bu4.w;
        *(float4*)&sm[QU_O + r * PSTR + fj * 4] = cvt_tf32x4(a);
        float4 kk4 = *(const float4*)&kmat[(long long)(m0 + r) * 256 + h * 32 + fj * 4];
        *(float4*)&sm[KT_O + r * PSTR + fj * 4] = cvt_tf32x4(kk4);
    }
    #pragma unroll
    for (int it = 0; it < 5; it++) {
        int e = tid + 256 * it;
        if (e < 129 * 8) {
            int r = e >> 3, fj = e & 7;
            float4 bv4 = *(const float4*)&pbv[h * 32 + fj * 4];
            int rv = q0 + da + r; if (rv > KTQ - 1) rv = KTQ - 1;
            float4 v = *(const float4*)&qb[(long long)rv * 256 + fj * 4];
            v.x += bv4.x; v.y += bv4.y; v.z += bv4.z; v.w += bv4.w;
            *(float4*)&sm[QV_O + r * PSTR + fj * 4] = cvt_tf32x4(v);
        }
    }
    #pragma unroll
    for (int it = 0; it < 8; it++) {
        int e = tid + 256 * it;
        int r = e >> 3, fj = e & 7;
        int d = dlo + r;
        int cm = d & 2047;
        float4 v = make_float4(0.f, 0.f, 0.f, 0.f);
        if (cm > 0 && r < 255)
            v = cvt_tf32x4(*(const float4*)&p[(long long)(cm - 1) * 256 + h * 32 + fj * 4]);
        *(float4*)&sm[PD_O + r * PSTR + fj * 4] = v;
    }
    __syncthreads();

    // ---- phase 1: banded G[r][ix] = Qv_sh[r] . Pd[ix] ----
    if (!boundary) {
        int s0b = (wy == 0) ? 64 : 0;   // band ix-window start (192 wide)
        float accg[4][6][4] = {};
        #pragma unroll
        for (int k0 = 0; k0 < 4; k0++) {
            int kk = k0 * 8;
            uint32_t a[4][4], bb[6][2];
            #pragma unroll
            for (int mi = 0; mi < 4; mi++) {
                int r0 = wy * 64 + mi * 16;
                a[mi][0] = __float_as_uint(sm[QV_O + (r0 + g) * PSTR + kk + t]);
                a[mi][1] = __float_as_uint(sm[QV_O + (r0 + g + 8) * PSTR + kk + t]);
                a[mi][2] = __float_as_uint(sm[QV_O + (r0 + g) * PSTR + kk + t + 4]);
                a[mi][3] = __float_as_uint(sm[QV_O + (r0 + g + 8) * PSTR + kk + t + 4]);
            }
            #pragma unroll
            for (int ni = 0; ni < 6; ni++) {
                int c0 = s0b + (wx * 6 + ni) * 8;
                bb[ni][0] = __float_as_uint(sm[PD_O + (c0 + g) * PSTR + kk + t]);
                bb[ni][1] = __float_as_uint(sm[PD_O + (c0 + g) * PSTR + kk + t + 4]);
            }
            #pragma unroll
            for (int mi = 0; mi < 4; mi++)
                #pragma unroll
                for (int ni = 0; ni < 6; ni++)
                    mma_tf32(accg[mi][ni], a[mi], bb[ni]);
        }
        #pragma unroll
        for (int mi = 0; mi < 4; mi++) {
            int r1 = wy * 64 + mi * 16 + g;
            #pragma unroll
            for (int ni = 0; ni < 6; ni++) {
                int cx = s0b + (wx * 6 + ni) * 8 + 2 * t;
                *(float2*)&sm[G_O + r1 * GSTR + cx] =
                    make_float2(accg[mi][ni][0], accg[mi][ni][1]);
                *(float2*)&sm[G_O + (r1 + 8) * GSTR + cx] =
                    make_float2(accg[mi][ni][2], accg[mi][ni][3]);
            }
        }
    } else {
        int trb = (tid >> 4) * 8, tcb = (tid & 15) * 8;
        #pragma unroll
        for (int i = 0; i < 8; i++) {
            int rr = trb + i;
            #pragma unroll
            for (int j = 0; j < 8; j++) {
                int c = tcb + j;
                int ix = c - rr + 127;
                int d = dlo + ix;
                int tt = rr + (d >> 11) - da;
                float s = 0.f;
                #pragma unroll
                for (int k = 0; k < 32; k++)
                    s += sm[QV_O + tt * PSTR + k] * sm[PD_O + ix * PSTR + k];
                sm[G_O + rr * GSTR + ix] = s;
            }
        }
    }
    __syncthreads();

    // ---- phase 2: ac = Qu . K^T ----
    float acc[4][4][4] = {};
    #pragma unroll
    for (int k0 = 0; k0 < 4; k0++) {
        int kk = k0 * 8;
        uint32_t a[4][4], bb[4][2];
        #pragma unroll
        for (int mi = 0; mi < 4; mi++) {
            int r0 = wy * 64 + mi * 16;
            a[mi][0] = __float_as_uint(sm[QU_O + (r0 + g) * PSTR + kk + t]);
            a[mi][1] = __float_as_uint(sm[QU_O + (r0 + g + 8) * PSTR + kk + t]);
            a[mi][2] = __float_as_uint(sm[QU_O + (r0 + g) * PSTR + kk + t + 4]);
            a[mi][3] = __float_as_uint(sm[QU_O + (r0 + g + 8) * PSTR + kk + t + 4]);
        }
        #pragma unroll
        for (int ni = 0; ni < 4; ni++) {
            int c0 = wx * 32 + ni * 8;
            bb[ni][0] = __float_as_uint(sm[KT_O + (c0 + g) * PSTR + kk + t]);
            bb[ni][1] = __float_as_uint(sm[KT_O + (c0 + g) * PSTR + kk + t + 4]);
        }
        #pragma unroll
        for (int mi = 0; mi < 4; mi++)
            #pragma unroll
            for (int ni = 0; ni < 4; ni++)
                mma_tf32(acc[mi][ni], a[mi], bb[ni]);
    }

    // ---- combine with bd, scale (keep in registers) ----
    const float sc = 0.17677669529663687f;
    #pragma unroll
    for (int mi = 0; mi < 4; mi++) {
        int r1 = wy * 64 + mi * 16 + g;
        int r2 = r1 + 8;
        #pragma unroll
        for (int ni = 0; ni < 4; ni++) {
            int cx = wx * 32 + ni * 8 + 2 * t;
            acc[mi][ni][0] = (acc[mi][ni][0] + sm[G_O + r1 * GSTR + cx     - r1 + 127]) * sc;
            acc[mi][ni][1] = (acc[mi][ni][1] + sm[G_O + r1 * GSTR + cx + 1 - r1 + 127]) * sc;
            acc[mi][ni][2] = (acc[mi][ni][2] + sm[G_O + r2 * GSTR + cx     - r2 + 127]) * sc;
            acc[mi][ni][3] = (acc[mi][ni][3] + sm[G_O + r2 * GSTR + cx + 1 - r2 + 127]) * sc;
        }
    }

    // ---- row-tile max reduce ----
    __syncthreads();
    float rm1[4], rm2[4];
    #pragma unroll
    for (int mi = 0; mi < 4; mi++) {
        int lr1 = wy * 64 + mi * 16 + g;
        int lr2 = lr1 + 8;
        float mx1 = -1e30f, mx2 = -1e30f;
        #pragma unroll
        for (int ni = 0; ni < 4; ni++) {
            mx1 = fmaxf(mx1, fmaxf(acc[mi][ni][0], acc[mi][ni][1]));
            mx2 = fmaxf(mx2, fmaxf(acc[mi][ni][2], acc[mi][ni][3]));
        }
        mx1 = fmaxf(mx1, __shfl_xor_sync(0xffffffffu, mx1, 1));
        mx1 = fmaxf(mx1, __shfl_xor_sync(0xffffffffu, mx1, 2));
        mx2 = fmaxf(mx2, __shfl_xor_sync(0xffffffffu, mx2, 1));
        mx2 = fmaxf(mx2, __shfl_xor_sync(0xffffffffu, mx2, 2));
        if (t == 0) {
            sm[SMAX_O + lr1 * 4 + wx] = mx1;
            sm[SMAX_O + lr2 * 4 + wx] = mx2;
        }
    }
    __syncthreads();

    // ---- exp + store exp(v - tile_max) + sum reduce ----
    #pragma unroll
    for (int mi = 0; mi < 4; mi++) {
        int lr1 = wy * 64 + mi * 16 + g;
        int lr2 = lr1 + 8;
        float a1 = fmaxf(fmaxf(sm[SMAX_O + lr1 * 4], sm[SMAX_O + lr1 * 4 + 1]),
                         fmaxf(sm[SMAX_O + lr1 * 4 + 2], sm[SMAX_O + lr1 * 4 + 3]));
        float a2 = fmaxf(fmaxf(sm[SMAX_O + lr2 * 4], sm[SMAX_O + lr2 * 4 + 1]),
                         fmaxf(sm[SMAX_O + lr2 * 4 + 2], sm[SMAX_O + lr2 * 4 + 3]));
        rm1[mi] = a1; rm2[mi] = a2;
        long long grow1 = ((long long)bh * KTQ + q0 + lr1) * KS + m0;
        long long grow2 = grow1 + 8 * KS;
        float s1 = 0.f, s2 = 0.f;
        #pragma unroll
        for (int ni = 0; ni < 4; ni++) {
            int cx = wx * 32 + ni * 8 + 2 * t;
            float e0 = __expf(acc[mi][ni][0] - a1);
            float e1 = __expf(acc[mi][ni][1] - a1);
            float e2 = __expf(acc[mi][ni][2] - a2);
            float e3 = __expf(acc[mi][ni][3] - a2);
            s1 += e0 + e1;
            s2 += e2 + e3;
            *(float2*)&ws[grow1 + cx] = make_float2(e0, e1);
            *(float2*)&ws[grow2 + cx] = make_float2(e2, e3);
        }
        s1 += __shfl_xor_sync(0xffffffffu, s1, 1);
        s1 += __shfl_xor_sync(0xffffffffu, s1, 2);
        s2 += __shfl_xor_sync(0xffffffffu, s2, 1);
        s2 += __shfl_xor_sync(0xffffffffu, s2, 2);
        if (t == 0) {
            sm[SSUM_O + lr1 * 4 + wx] = s1;
            sm[SSUM_O + lr2 * 4 + wx] = s2;
        }
    }
    __syncthreads();
    if (wx == 0 && t == 0) {
        int my = m0 >> 7;
        long long sb = ((long long)bh * 8 + my) * KTQ + q0;
        #pragma unroll
        for (int mi = 0; mi < 4; mi++) {
            int lr1 = wy * 64 + mi * 16 + g;
            int lr2 = lr1 + 8;
            float s1 = sm[SSUM_O + lr1 * 4] + sm[SSUM_O + lr1 * 4 + 1]
                     + sm[SSUM_O + lr1 * 4 + 2] + sm[SSUM_O + lr1 * 4 + 3];
            float s2 = sm[SSUM_O + lr2 * 4] + sm[SSUM_O + lr2 * 4 + 1]
                     + sm[SSUM_O + lr2 * 4 + 2] + sm[SSUM_O + lr2 * 4 + 3];
            gstats[sb + lr1] = make_float2(rm1[mi], s1);
            gstats[sb + lr2] = make_float2(rm2[mi], s2);
        }
    }
}

// =============== av fused: single-multiply normalize + attn@V ===============
// ws holds exp(v - tile_max); p = stored * f, f = exp(tile_max - M) * inv.
#define AVSTR 68
#define AV_A 0
#define AV_V 8704
#define AV_M 10880
#define AV_I 11008
#define AV_S 11136
#define AV_F 13184
#define AV_SMEM (14208 * 4)

__global__ __launch_bounds__(256) void av_fused(
    float* __restrict__ ws, const float* __restrict__ vmat,
    const float2* __restrict__ gstats, float* __restrict__ ao)
{
    extern __shared__ float sv[];
    float2* sSt = (float2*)(sv + AV_S);
    int q0 = blockIdx.x * 128;
    int bh = blockIdx.y;
    int b = bh >> 3, h = bh & 7;
    int tid = threadIdx.x;
    int wid = tid >> 5, lane = tid & 31;
    int g = lane >> 2, t = lane & 3;

    for (int idx = tid; idx < 1024; idx += 256)
        sSt[idx] = gstats[(((long long)bh * 8 + (idx >> 7)) << 12) + q0 + (idx & 127)];
    __syncthreads();
    if (tid < 128) {
        float M = -1e30f;
        #pragma unroll
        for (int mt = 0; mt < 8; mt++) M = fmaxf(M, sSt[mt * 128 + tid].x);
        float s = 0.f;
        #pragma unroll
        for (int mt = 0; mt < 8; mt++)
            s += sSt[mt * 128 + tid].y * __expf(sSt[mt * 128 + tid].x - M);
        sv[AV_M + tid] = M;
        sv[AV_I + tid] = 1.f / s;
    }
    __syncthreads();
    // per-(row, m-tile) factors
    for (int idx = tid; idx < 1024; idx += 256) {
        int r = idx & 127;
        sv[AV_F + idx] = __expf(sSt[idx].x - sv[AV_M + r]) * sv[AV_I + r];
    }
    __syncthreads();

    float* wsrow = ws + ((long long)bh * KTQ + q0) * KS;
    float acc[4][4] = {};

    for (int s0 = 0; s0 < KS; s0 += 64) {
        int ftile = (s0 >> 7) << 7;
        #pragma unroll
        for (int it = 0; it < 8; it++) {
            int e = tid + 256 * it;
            int r = e >> 4, f = e & 15;
            float4 raw = *(float4*)&wsrow[(long long)r * KS + s0 + f * 4];
            float fac = sv[AV_F + ftile + r];
            float4 pp;
            pp.x = raw.x * fac;
            pp.y = raw.y * fac;
            pp.z = raw.z * fac;
            pp.w = raw.w * fac;
            *(float4*)&wsrow[(long long)r * KS + s0 + f * 4] = pp;
            *(float4*)&sv[AV_A + r * AVSTR + f * 4] = cvt_tf32x4(pp);
        }
        #pragma unroll
        for (int it = 0; it < 8; it++) {
            int e = tid + 256 * it;
            int k = e >> 5, n = e & 31;
            sv[AV_V + n * AVSTR + k] =
                cvt_tf32(vmat[(long long)(s0 + k) * 256 + h * 32 + n]);
        }
        __syncthreads();
        int r0 = wid * 16;
        #pragma unroll
        for (int k0 = 0; k0 < 8; k0++) {
            int kk = k0 * 8;
            uint32_t a[4];
            a[0] = __float_as_uint(sv[AV_A + (r0 + g) * AVSTR + kk + t]);
            a[1] = __float_as_uint(sv[AV_A + (r0 + g + 8) * AVSTR + kk + t]);
            a[2] = __float_as_uint(sv[AV_A + (r0 + g) * AVSTR + kk + t + 4]);
            a[3] = __float_as_uint(sv[AV_A + (r0 + g + 8) * AVSTR + kk + t + 4]);
            #pragma unroll
            for (int ni = 0; ni < 4; ni++) {
                uint32_t bb[2];
                bb[0] = __float_as_uint(sv[AV_V + (ni * 8 + g) * AVSTR + kk + t]);
                bb[1] = __float_as_uint(sv[AV_V + (ni * 8 + g) * AVSTR + kk + t + 4]);
                mma_tf32(acc[ni], a, bb);
            }
        }
        __syncthreads();
    }
    int r1 = q0 + wid * 16 + g;
    float* aob = ao + ((long long)b * KTQ + r1) * 256 + h * 32;
    #pragma unroll
    for (int ni = 0; ni < 4; ni++) {
        int cx = ni * 8 + 2 * t;
        *(float2*)&aob[cx]           = make_float2(acc[ni][0], acc[ni][1]);
        *(float2*)&aob[8 * 256 + cx] = make_float2(acc[ni][2], acc[ni][3]);
    }
}

// ---------------------------------------------------------------------------
extern "C" void kernel_launch(void* const* d_in, const int* in_sizes, int n_in,
                              void* d_out, int out_size)
{
    const float* vis  = (const float*)d_in[0];
    const float* mem  = (const float*)d_in[1];
    const float* Wq   = (const float*)d_in[3];
    const float* bq   = (const float*)d_in[4];
    const float* Wk   = (const float*)d_in[5];
    const float* bk   = (const float*)d_in[6];
    const float* Wv   = (const float*)d_in[7];
    const float* bv   = (const float*)d_in[8];
    const float* Wo   = (const float*)d_in[9];
    const float* bo   = (const float*)d_in[10];
    const float* Wpos = (const float*)d_in[11];
    const float* pbu  = (const float*)d_in[12];
    const float* pbv  = (const float*)d_in[13];

    float* out    = (float*)d_out;
    float* out_ws = out + XE;

    float* scratch = nullptr;
    cudaGetSymbolAddress((void**)&scratch, g_scratch);
    float* pe = scratch;
    float* pp = pe + 524032;
    float* kk = pp + 4 * 524032;
    float* vv = kk + 4 * 262144;
    float* qq = vv + 4 * 262144;
    float* xx = qq + XE;
    float* ao = xx + XE;
    float2* gstats = (float2*)(ao + XE);

    cudaFuncSetAttribute(scores_mma_kernel,
        cudaFuncAttributeMaxDynamicSharedMemorySize, SC_SMEM);
    cudaFuncSetAttribute(proj_mma,
        cudaFuncAttributeMaxDynamicSharedMemorySize, PJ_SMEM);
    cudaFuncSetAttribute(av_fused,
        cudaFuncAttributeMaxDynamicSharedMemorySize, AV_SMEM);

    pe_kernel<<<KP, 128>>>(pe);

    proj_mma<<<dim3(8, 2, 2 * KL), 512, PJ_SMEM>>>(mem, Wk, bk, kk, KS, 65536, 262144,
                                                   Wv, bv, vv, KL);
    proj_mma<<<dim3(16, 2, KL), 512, PJ_SMEM>>>(pe, Wpos, nullptr, pp, KP, 65536, 524032,
                                                nullptr, nullptr, nullptr, 1 << 30);

    const float* cur = vis;
    for (int l = 0; l < KL; l++) {
        proj_mma<<<dim3(64, 2, 1), 512, PJ_SMEM>>>(cur, Wq + l * 65536, bq + l * 256,
                                                   qq, KB * KTQ, 0, 0,
                                                   nullptr, nullptr, nullptr, 1 << 30);
        float* wsl = out_ws + (long long)l * KB * KH * KTQ * KS;
        scores_mma_kernel<<<dim3(32, 8, 16), 256, SC_SMEM>>>(
            qq, kk + l * 262144, pp + l * 524032,
            pbu + l * 256, pbv + l * 256, wsl, gstats);
        av_fused<<<dim3(32, 16), 256, AV_SMEM>>>(wsl, vv + l * 262144, gstats, ao);
        float* nxt = (l == KL - 1) ? out : xx;
        proj_mma<<<dim3(64, 2, 1), 512, PJ_SMEM>>>(ao, Wo + l * 65536, bo + l * 256,
                                                   nxt, KB * KTQ, 0, 0,
                                                   nullptr, nullptr, nullptr, 1 << 30);
        cur = nxt;
    }
}

// round 12
// speedup vs baseline: 1.2405x; 1.0665x over previous
#include <cuda_runtime.h>
#include <cuda_fp16.h>
#include <math.h>
#include <stdint.h>

#define KB   2
#define KTQ  4096
#define KS   1024
#define KD   256
#define KH   8
#define KL   4
#define KP   2047
#define XE   (KB*KTQ*KD)

// pe | pp(x4) | kk(x4) | vv(x4) | qq | xx | ao | stats(float2 x 524288)
__device__ float g_scratch[12057344];
// fp16 exp scratch for one layer of ws (reused across layers)
__device__ __half g_ews[67108864];

// ===================== mma.sync tf32 m16n8k8 helpers ========================
__device__ __forceinline__ void mma_tf32(float* c, const uint32_t* a, const uint32_t* b) {
    asm volatile("mma.sync.aligned.m16n8k8.row.col.f32.tf32.tf32.f32 "
        "{%0,%1,%2,%3}, {%4,%5,%6,%7}, {%8,%9}, {%0,%1,%2,%3};\n"
        : "+f"(c[0]), "+f"(c[1]), "+f"(c[2]), "+f"(c[3])
        : "r"(a[0]), "r"(a[1]), "r"(a[2]), "r"(a[3]), "r"(b[0]), "r"(b[1]));
}
__device__ __forceinline__ float cvt_tf32(float x) {
    float y;
    asm("cvt.rna.tf32.f32 %0, %1;" : "=f"(y) : "f"(x));
    return y;
}
__device__ __forceinline__ float4 cvt_tf32x4(float4 v) {
    v.x = cvt_tf32(v.x); v.y = cvt_tf32(v.y);
    v.z = cvt_tf32(v.z); v.w = cvt_tf32(v.w);
    return v;
}

// ============================ pe =================================
__global__ void pe_kernel(float* __restrict__ pe) {
    int i = blockIdx.x;
    int j = threadIdx.x;
    double div = exp(-(double)j * 9.210340371976184 / 128.0);
    double a = (1023.0 - (double)i) * div;
    pe[i * KD + 2 * j]     = (float)sin(a);
    pe[i * KD + 2 * j + 1] = (float)cos(a);
}

// ================= proj via 3xTF32 mma, 512 threads =========================
#define PJSTR 36
#define PJ_AB 0
#define PJ_AS 4608
#define PJ_WB 9216
#define PJ_WS 13824
#define PJ_SMEM (18432 * 4)

__global__ __launch_bounds__(512) void proj_mma(
    const float* __restrict__ A, const float* __restrict__ W,
    const float* __restrict__ bias, float* __restrict__ C,
    int M, int wStride, int cStride,
    const float* __restrict__ W2, const float* __restrict__ bias2,
    float* __restrict__ C2, int zSplit)
{
    extern __shared__ float sp[];
    int m0 = blockIdx.x * 128, n0 = blockIdx.y * 128;
    int z = blockIdx.z;
    if (z >= zSplit) { W = W2; bias = bias2; C = C2; z -= zSplit; }
    W += (long long)z * wStride;
    C += (long long)z * cStride;
    if (bias) bias += z * 256;
    int tid = threadIdx.x;
    int wid = tid >> 5, lane = tid & 31;
    int wy = wid >> 2, wx = wid & 3;
    int g = lane >> 2, t = lane & 3;
    float acc[2][4][4] = {};

    for (int k0 = 0; k0 < 256; k0 += 32) {
        #pragma unroll
        for (int it = 0; it < 2; it++) {
            int e = tid + 512 * it;
            int r = e >> 3, f = e & 7;
            int row = m0 + r;
            float4 a4 = (row < M) ? *(const float4*)&A[(long long)row * 256 + k0 + f * 4]
                                  : make_float4(0.f, 0.f, 0.f, 0.f);
            float4 ab = cvt_tf32x4(a4);
            float4 as = make_float4(a4.x - ab.x, a4.y - ab.y, a4.z - ab.z, a4.w - ab.w);
            *(float4*)&sp[PJ_AB + r * PJSTR + f * 4] = ab;
            *(float4*)&sp[PJ_AS + r * PJSTR + f * 4] = cvt_tf32x4(as);
            float4 w4 = *(const float4*)&W[(long long)(n0 + r) * 256 + k0 + f * 4];
            float4 wb = cvt_tf32x4(w4);
            float4 ws4 = make_float4(w4.x - wb.x, w4.y - wb.y, w4.z - wb.z, w4.w - wb.w);
            *(float4*)&sp[PJ_WB + r * PJSTR + f * 4] = wb;
            *(float4*)&sp[PJ_WS + r * PJSTR + f * 4] = cvt_tf32x4(ws4);
        }
        __syncthreads();
        #pragma unroll
        for (int k0i = 0; k0i < 4; k0i++) {
            int kk = k0i * 8;
            uint32_t aB[2][4], aS[2][4], bB[4][2], bS[4][2];
            #pragma unroll
            for (int mi = 0; mi < 2; mi++) {
                int r0 = wy * 32 + mi * 16;
                aB[mi][0] = __float_as_uint(sp[PJ_AB + (r0 + g) * PJSTR + kk + t]);
                aB[mi][1] = __float_as_uint(sp[PJ_AB + (r0 + g + 8) * PJSTR + kk + t]);
                aB[mi][2] = __float_as_uint(sp[PJ_AB + (r0 + g) * PJSTR + kk + t + 4]);
                aB[mi][3] = __float_as_uint(sp[PJ_AB + (r0 + g + 8) * PJSTR + kk + t + 4]);
                aS[mi][0] = __float_as_uint(sp[PJ_AS + (r0 + g) * PJSTR + kk + t]);
                aS[mi][1] = __float_as_uint(sp[PJ_AS + (r0 + g + 8) * PJSTR + kk + t]);
                aS[mi][2] = __float_as_uint(sp[PJ_AS + (r0 + g) * PJSTR + kk + t + 4]);
                aS[mi][3] = __float_as_uint(sp[PJ_AS + (r0 + g + 8) * PJSTR + kk + t + 4]);
            }
            #pragma unroll
            for (int ni = 0; ni < 4; ni++) {
                int c0 = wx * 32 + ni * 8;
                bB[ni][0] = __float_as_uint(sp[PJ_WB + (c0 + g) * PJSTR + kk + t]);
                bB[ni][1] = __float_as_uint(sp[PJ_WB + (c0 + g) * PJSTR + kk + t + 4]);
                bS[ni][0] = __float_as_uint(sp[PJ_WS + (c0 + g) * PJSTR + kk + t]);
                bS[ni][1] = __float_as_uint(sp[PJ_WS + (c0 + g) * PJSTR + kk + t + 4]);
            }
            #pragma unroll
            for (int mi = 0; mi < 2; mi++)
                #pragma unroll
                for (int ni = 0; ni < 4; ni++) {
                    mma_tf32(acc[mi][ni], aB[mi], bS[ni]);
                    mma_tf32(acc[mi][ni], aS[mi], bB[ni]);
                    mma_tf32(acc[mi][ni], aB[mi], bB[ni]);
                }
        }
        __syncthreads();
    }
    #pragma unroll
    for (int mi = 0; mi < 2; mi++) {
        int r1 = m0 + wy * 32 + mi * 16 + g;
        int r2 = r1 + 8;
        #pragma unroll
        for (int ni = 0; ni < 4; ni++) {
            int cx = wx * 32 + ni * 8 + 2 * t;
            float b0 = bias ? bias[n0 + cx] : 0.f;
            float b1 = bias ? bias[n0 + cx + 1] : 0.f;
            if (r1 < M)
                *(float2*)&C[(long long)r1 * 256 + n0 + cx] =
                    make_float2(acc[mi][ni][0] + b0, acc[mi][ni][1] + b1);
            if (r2 < M)
                *(float2*)&C[(long long)r2 * 256 + n0 + cx] =
                    make_float2(acc[mi][ni][2] + b0, acc[mi][ni][3] + b1);
        }
    }
}

// ====================== scores via mma.sync tf32, 256 threads ===============
// Banded G phase (R9). Epilogue stores exp(v - tile_max) as fp16 into ews.
#define PSTR 36
#define QU_O 0
#define KT_O 4608
#define QV_O 9216
#define PD_O 13860
#define G_O  23076
#define GSTR 260
#define SMAX_O (G_O + 128 * GSTR)
#define SSUM_O (SMAX_O + 512)
#define SC_FLOATS (SSUM_O + 512)
#define SC_SMEM (SC_FLOATS * 4)

__global__ __launch_bounds__(256, 1) void scores_mma_kernel(
    const float* __restrict__ q, const float* __restrict__ kmat,
    const float* __restrict__ p, const float* __restrict__ pbu,
    const float* __restrict__ pbv, __half* __restrict__ ews,
    float2* __restrict__ gstats)
{
    extern __shared__ float sm[];
    int q0 = blockIdx.x * 128, m0 = blockIdx.y * 128;
    int bh = blockIdx.z;
    int b = bh >> 3, h = bh & 7;
    int tid = threadIdx.x;
    int wid = tid >> 5, lane = tid & 31;
    int wy = wid >> 2, wx = wid & 3;        // 2x4 warp grid
    int g = lane >> 2, t = lane & 3;

    int dlo = m0 - q0 + 3969;
    int da  = dlo >> 11;
    bool boundary = ((dlo >> 11) != ((dlo + 254) >> 11));

    const float* qb = q + (long long)b * KTQ * 256 + h * 32;
    #pragma unroll
    for (int it = 0; it < 4; it++) {
        int e = tid + 256 * it;
        int r = e >> 3, fj = e & 7;
        float4 bu4 = *(const float4*)&pbu[h * 32 + fj * 4];
        float4 a = *(const float4*)&qb[(long long)(q0 + r) * 256 + fj * 4];
        a.x += bu4.x; a.y += bu4.y; a.z += bu4.z; a.w += bu4.w;
        *(float4*)&sm[QU_O + r * PSTR + fj * 4] = cvt_tf32x4(a);
        float4 kk4 = *(const float4*)&kmat[(long long)(m0 + r) * 256 + h * 32 + fj * 4];
        *(float4*)&sm[KT_O + r * PSTR + fj * 4] = cvt_tf32x4(kk4);
    }
    #pragma unroll
    for (int it = 0; it < 5; it++) {
        int e = tid + 256 * it;
        if (e < 129 * 8) {
            int r = e >> 3, fj = e & 7;
            float4 bv4 = *(const float4*)&pbv[h * 32 + fj * 4];
            int rv = q0 + da + r; if (rv > KTQ - 1) rv = KTQ - 1;
            float4 v = *(const float4*)&qb[(long long)rv * 256 + fj * 4];
            v.x += bv4.x; v.y += bv4.y; v.z += bv4.z; v.w += bv4.w;
            *(float4*)&sm[QV_O + r * PSTR + fj * 4] = cvt_tf32x4(v);
        }
    }
    #pragma unroll
    for (int it = 0; it < 8; it++) {
        int e = tid + 256 * it;
        int r = e >> 3, fj = e & 7;
        int d = dlo + r;
        int cm = d & 2047;
        float4 v = make_float4(0.f, 0.f, 0.f, 0.f);
        if (cm > 0 && r < 255)
            v = cvt_tf32x4(*(const float4*)&p[(long long)(cm - 1) * 256 + h * 32 + fj * 4]);
        *(float4*)&sm[PD_O + r * PSTR + fj * 4] = v;
    }
    __syncthreads();

    // ---- phase 1: banded G[r][ix] = Qv_sh[r] . Pd[ix] ----
    if (!boundary) {
        int s0b = (wy == 0) ? 64 : 0;
        float accg[4][6][4] = {};
        #pragma unroll
        for (int k0 = 0; k0 < 4; k0++) {
            int kk = k0 * 8;
            uint32_t a[4][4], bb[6][2];
            #pragma unroll
            for (int mi = 0; mi < 4; mi++) {
                int r0 = wy * 64 + mi * 16;
                a[mi][0] = __float_as_uint(sm[QV_O + (r0 + g) * PSTR + kk + t]);
                a[mi][1] = __float_as_uint(sm[QV_O + (r0 + g + 8) * PSTR + kk + t]);
                a[mi][2] = __float_as_uint(sm[QV_O + (r0 + g) * PSTR + kk + t + 4]);
                a[mi][3] = __float_as_uint(sm[QV_O + (r0 + g + 8) * PSTR + kk + t + 4]);
            }
            #pragma unroll
            for (int ni = 0; ni < 6; ni++) {
                int c0 = s0b + (wx * 6 + ni) * 8;
                bb[ni][0] = __float_as_uint(sm[PD_O + (c0 + g) * PSTR + kk + t]);
                bb[ni][1] = __float_as_uint(sm[PD_O + (c0 + g) * PSTR + kk + t + 4]);
            }
            #pragma unroll
            for (int mi = 0; mi < 4; mi++)
                #pragma unroll
                for (int ni = 0; ni < 6; ni++)
                    mma_tf32(accg[mi][ni], a[mi], bb[ni]);
        }
        #pragma unroll
        for (int mi = 0; mi < 4; mi++) {
            int r1 = wy * 64 + mi * 16 + g;
            #pragma unroll
            for (int ni = 0; ni < 6; ni++) {
                int cx = s0b + (wx * 6 + ni) * 8 + 2 * t;
                *(float2*)&sm[G_O + r1 * GSTR + cx] =
                    make_float2(accg[mi][ni][0], accg[mi][ni][1]);
                *(float2*)&sm[G_O + (r1 + 8) * GSTR + cx] =
                    make_float2(accg[mi][ni][2], accg[mi][ni][3]);
            }
        }
    } else {
        int trb = (tid >> 4) * 8, tcb = (tid & 15) * 8;
        #pragma unroll
        for (int i = 0; i < 8; i++) {
            int rr = trb + i;
            #pragma unroll
            for (int j = 0; j < 8; j++) {
                int c = tcb + j;
                int ix = c - rr + 127;
                int d = dlo + ix;
                int tt = rr + (d >> 11) - da;
                float s = 0.f;
                #pragma unroll
                for (int k = 0; k < 32; k++)
                    s += sm[QV_O + tt * PSTR + k] * sm[PD_O + ix * PSTR + k];
                sm[G_O + rr * GSTR + ix] = s;
            }
        }
    }
    __syncthreads();

    // ---- phase 2: ac = Qu . K^T ----
    float acc[4][4][4] = {};
    #pragma unroll
    for (int k0 = 0; k0 < 4; k0++) {
        int kk = k0 * 8;
        uint32_t a[4][4], bb[4][2];
        #pragma unroll
        for (int mi = 0; mi < 4; mi++) {
            int r0 = wy * 64 + mi * 16;
            a[mi][0] = __float_as_uint(sm[QU_O + (r0 + g) * PSTR + kk + t]);
            a[mi][1] = __float_as_uint(sm[QU_O + (r0 + g + 8) * PSTR + kk + t]);
            a[mi][2] = __float_as_uint(sm[QU_O + (r0 + g) * PSTR + kk + t + 4]);
            a[mi][3] = __float_as_uint(sm[QU_O + (r0 + g + 8) * PSTR + kk + t + 4]);
        }
        #pragma unroll
        for (int ni = 0; ni < 4; ni++) {
            int c0 = wx * 32 + ni * 8;
            bb[ni][0] = __float_as_uint(sm[KT_O + (c0 + g) * PSTR + kk + t]);
            bb[ni][1] = __float_as_uint(sm[KT_O + (c0 + g) * PSTR + kk + t + 4]);
        }
        #pragma unroll
        for (int mi = 0; mi < 4; mi++)
            #pragma unroll
            for (int ni = 0; ni < 4; ni++)
                mma_tf32(acc[mi][ni], a[mi], bb[ni]);
    }

    // ---- combine with bd, scale (keep in registers) ----
    const float sc = 0.17677669529663687f;
    #pragma unroll
    for (int mi = 0; mi < 4; mi++) {
        int r1 = wy * 64 + mi * 16 + g;
        int r2 = r1 + 8;
        #pragma unroll
        for (int ni = 0; ni < 4; ni++) {
            int cx = wx * 32 + ni * 8 + 2 * t;
            acc[mi][ni][0] = (acc[mi][ni][0] + sm[G_O + r1 * GSTR + cx     - r1 + 127]) * sc;
            acc[mi][ni][1] = (acc[mi][ni][1] + sm[G_O + r1 * GSTR + cx + 1 - r1 + 127]) * sc;
            acc[mi][ni][2] = (acc[mi][ni][2] + sm[G_O + r2 * GSTR + cx     - r2 + 127]) * sc;
            acc[mi][ni][3] = (acc[mi][ni][3] + sm[G_O + r2 * GSTR + cx + 1 - r2 + 127]) * sc;
        }
    }

    // ---- row-tile max reduce ----
    __syncthreads();
    float rm1[4], rm2[4];
    #pragma unroll
    for (int mi = 0; mi < 4; mi++) {
        int lr1 = wy * 64 + mi * 16 + g;
        int lr2 = lr1 + 8;
        float mx1 = -1e30f, mx2 = -1e30f;
        #pragma unroll
        for (int ni = 0; ni < 4; ni++) {
            mx1 = fmaxf(mx1, fmaxf(acc[mi][ni][0], acc[mi][ni][1]));
            mx2 = fmaxf(mx2, fmaxf(acc[mi][ni][2], acc[mi][ni][3]));
        }
        mx1 = fmaxf(mx1, __shfl_xor_sync(0xffffffffu, mx1, 1));
        mx1 = fmaxf(mx1, __shfl_xor_sync(0xffffffffu, mx1, 2));
        mx2 = fmaxf(mx2, __shfl_xor_sync(0xffffffffu, mx2, 1));
        mx2 = fmaxf(mx2, __shfl_xor_sync(0xffffffffu, mx2, 2));
        if (t == 0) {
            sm[SMAX_O + lr1 * 4 + wx] = mx1;
            sm[SMAX_O + lr2 * 4 + wx] = mx2;
        }
    }
    __syncthreads();

    // ---- exp + store fp16 exp(v - tile_max) + sum reduce ----
    #pragma unroll
    for (int mi = 0; mi < 4; mi++) {
        int lr1 = wy * 64 + mi * 16 + g;
        int lr2 = lr1 + 8;
        float a1 = fmaxf(fmaxf(sm[SMAX_O + lr1 * 4], sm[SMAX_O + lr1 * 4 + 1]),
                         fmaxf(sm[SMAX_O + lr1 * 4 + 2], sm[SMAX_O + lr1 * 4 + 3]));
        float a2 = fmaxf(fmaxf(sm[SMAX_O + lr2 * 4], sm[SMAX_O + lr2 * 4 + 1]),
                         fmaxf(sm[SMAX_O + lr2 * 4 + 2], sm[SMAX_O + lr2 * 4 + 3]));
        rm1[mi] = a1; rm2[mi] = a2;
        long long grow1 = ((long long)bh * KTQ + q0 + lr1) * KS + m0;
        long long grow2 = grow1 + 8 * KS;
        float s1 = 0.f, s2 = 0.f;
        #pragma unroll
        for (int ni = 0; ni < 4; ni++) {
            int cx = wx * 32 + ni * 8 + 2 * t;
            float e0 = __expf(acc[mi][ni][0] - a1);
            float e1 = __expf(acc[mi][ni][1] - a1);
            float e2 = __expf(acc[mi][ni][2] - a2);
            float e3 = __expf(acc[mi][ni][3] - a2);
            s1 += e0 + e1;
            s2 += e2 + e3;
            *(__half2*)&ews[grow1 + cx] = __floats2half2_rn(e0, e1);
            *(__half2*)&ews[grow2 + cx] = __floats2half2_rn(e2, e3);
        }
        s1 += __shfl_xor_sync(0xffffffffu, s1, 1);
        s1 += __shfl_xor_sync(0xffffffffu, s1, 2);
        s2 += __shfl_xor_sync(0xffffffffu, s2, 1);
        s2 += __shfl_xor_sync(0xffffffffu, s2, 2);
        if (t == 0) {
            sm[SSUM_O + lr1 * 4 + wx] = s1;
            sm[SSUM_O + lr2 * 4 + wx] = s2;
        }
    }
    __syncthreads();
    if (wx == 0 && t == 0) {
        int my = m0 >> 7;
        long long sb = ((long long)bh * 8 + my) * KTQ + q0;
        #pragma unroll
        for (int mi = 0; mi < 4; mi++) {
            int lr1 = wy * 64 + mi * 16 + g;
            int lr2 = lr1 + 8;
            float s1 = sm[SSUM_O + lr1 * 4] + sm[SSUM_O + lr1 * 4 + 1]
                     + sm[SSUM_O + lr1 * 4 + 2] + sm[SSUM_O + lr1 * 4 + 3];
            float s2 = sm[SSUM_O + lr2 * 4] + sm[SSUM_O + lr2 * 4 + 1]
                     + sm[SSUM_O + lr2 * 4 + 2] + sm[SSUM_O + lr2 * 4 + 3];
            gstats[sb + lr1] = make_float2(rm1[mi], s1);
            gstats[sb + lr2] = make_float2(rm2[mi], s2);
        }
    }
}

// ======= av fused: fp16 exp read -> normalize -> fp32 ws + attn@V ==========
#define AVSTR 68
#define AV_A 0
#define AV_V 8704
#define AV_M 10880
#define AV_I 11008
#define AV_S 11136
#define AV_F 13184
#define AV_SMEM (14208 * 4)

__global__ __launch_bounds__(256) void av_fused(
    const __half* __restrict__ ews, float* __restrict__ ws,
    const float* __restrict__ vmat,
    const float2* __restrict__ gstats, float* __restrict__ ao)
{
    extern __shared__ float sv[];
    float2* sSt = (float2*)(sv + AV_S);
    int q0 = blockIdx.x * 128;
    int bh = blockIdx.y;
    int b = bh >> 3, h = bh & 7;
    int tid = threadIdx.x;
    int wid = tid >> 5, lane = tid & 31;
    int g = lane >> 2, t = lane & 3;

    for (int idx = tid; idx < 1024; idx += 256)
        sSt[idx] = gstats[(((long long)bh * 8 + (idx >> 7)) << 12) + q0 + (idx & 127)];
    __syncthreads();
    if (tid < 128) {
        float M = -1e30f;
        #pragma unroll
        for (int mt = 0; mt < 8; mt++) M = fmaxf(M, sSt[mt * 128 + tid].x);
        float s = 0.f;
        #pragma unroll
        for (int mt = 0; mt < 8; mt++)
            s += sSt[mt * 128 + tid].y * __expf(sSt[mt * 128 + tid].x - M);
        sv[AV_M + tid] = M;
        sv[AV_I + tid] = 1.f / s;
    }
    __syncthreads();
    for (int idx = tid; idx < 1024; idx += 256) {
        int r = idx & 127;
        sv[AV_F + idx] = __expf(sSt[idx].x - sv[AV_M + r]) * sv[AV_I + r];
    }
    __syncthreads();

    const __half* ewsrow = ews + ((long long)bh * KTQ + q0) * KS;
    float* wsrow = ws + ((long long)bh * KTQ + q0) * KS;
    float acc[4][4] = {};

    for (int s0 = 0; s0 < KS; s0 += 64) {
        int ftile = (s0 >> 7) << 7;
        #pragma unroll
        for (int it = 0; it < 8; it++) {
            int e = tid + 256 * it;
            int r = e >> 4, f = e & 15;
            long long off = (long long)r * KS + s0 + f * 4;
            uint2 rh = *(const uint2*)&ewsrow[off];
            __half2 h0 = *reinterpret_cast<__half2*>(&rh.x);
            __half2 h1 = *reinterpret_cast<__half2*>(&rh.y);
            float2 e0 = __half22float2(h0);
            float2 e1 = __half22float2(h1);
            float fac = sv[AV_F + ftile + r];
            float4 pp;
            pp.x = e0.x * fac; pp.y = e0.y * fac;
            pp.z = e1.x * fac; pp.w = e1.y * fac;
            *(float4*)&wsrow[off] = pp;
            *(float4*)&sv[AV_A + r * AVSTR + f * 4] = cvt_tf32x4(pp);
        }
        #pragma unroll
        for (int it = 0; it < 8; it++) {
            int e = tid + 256 * it;
            int k = e >> 5, n = e & 31;
            sv[AV_V + n * AVSTR + k] =
                cvt_tf32(vmat[(long long)(s0 + k) * 256 + h * 32 + n]);
        }
        __syncthreads();
        int r0 = wid * 16;
        #pragma unroll
        for (int k0 = 0; k0 < 8; k0++) {
            int kk = k0 * 8;
            uint32_t a[4];
            a[0] = __float_as_uint(sv[AV_A + (r0 + g) * AVSTR + kk + t]);
            a[1] = __float_as_uint(sv[AV_A + (r0 + g + 8) * AVSTR + kk + t]);
            a[2] = __float_as_uint(sv[AV_A + (r0 + g) * AVSTR + kk + t + 4]);
            a[3] = __float_as_uint(sv[AV_A + (r0 + g + 8) * AVSTR + kk + t + 4]);
            #pragma unroll
            for (int ni = 0; ni < 4; ni++) {
                uint32_t bb[2];
                bb[0] = __float_as_uint(sv[AV_V + (ni * 8 + g) * AVSTR + kk + t]);
                bb[1] = __float_as_uint(sv[AV_V + (ni * 8 + g) * AVSTR + kk + t + 4]);
                mma_tf32(acc[ni], a, bb);
            }
        }
        __syncthreads();
    }
    int r1 = q0 + wid * 16 + g;
    float* aob = ao + ((long long)b * KTQ + r1) * 256 + h * 32;
    #pragma unroll
    for (int ni = 0; ni < 4; ni++) {
        int cx = ni * 8 + 2 * t;
        *(float2*)&aob[cx]           = make_float2(acc[ni][0], acc[ni][1]);
        *(float2*)&aob[8 * 256 + cx] = make_float2(acc[ni][2], acc[ni][3]);
    }
}

// ---------------------------------------------------------------------------
extern "C" void kernel_launch(void* const* d_in, const int* in_sizes, int n_in,
                              void* d_out, int out_size)
{
    const float* vis  = (const float*)d_in[0];
    const float* mem  = (const float*)d_in[1];
    const float* Wq   = (const float*)d_in[3];
    const float* bq   = (const float*)d_in[4];
    const float* Wk   = (const float*)d_in[5];
    const float* bk   = (const float*)d_in[6];
    const float* Wv   = (const float*)d_in[7];
    const float* bv   = (const float*)d_in[8];
    const float* Wo   = (const float*)d_in[9];
    const float* bo   = (const float*)d_in[10];
    const float* Wpos = (const float*)d_in[11];
    const float* pbu  = (const float*)d_in[12];
    const float* pbv  = (const float*)d_in[13];

    float* out    = (float*)d_out;
    float* out_ws = out + XE;

    float* scratch = nullptr;
    cudaGetSymbolAddress((void**)&scratch, g_scratch);
    __half* ews = nullptr;
    cudaGetSymbolAddress((void**)&ews, g_ews);
    float* pe = scratch;
    float* pp = pe + 524032;
    float* kk = pp + 4 * 524032;
    float* vv = kk + 4 * 262144;
    float* qq = vv + 4 * 262144;
    float* xx = qq + XE;
    float* ao = xx + XE;
    float2* gstats = (float2*)(ao + XE);

    cudaFuncSetAttribute(scores_mma_kernel,
        cudaFuncAttributeMaxDynamicSharedMemorySize, SC_SMEM);
    cudaFuncSetAttribute(proj_mma,
        cudaFuncAttributeMaxDynamicSharedMemorySize, PJ_SMEM);
    cudaFuncSetAttribute(av_fused,
        cudaFuncAttributeMaxDynamicSharedMemorySize, AV_SMEM);

    pe_kernel<<<KP, 128>>>(pe);

    proj_mma<<<dim3(8, 2, 2 * KL), 512, PJ_SMEM>>>(mem, Wk, bk, kk, KS, 65536, 262144,
                                                   Wv, bv, vv, KL);
    proj_mma<<<dim3(16, 2, KL), 512, PJ_SMEM>>>(pe, Wpos, nullptr, pp, KP, 65536, 524032,
                                                nullptr, nullptr, nullptr, 1 << 30);

    const float* cur = vis;
    for (int l = 0; l < KL; l++) {
        proj_mma<<<dim3(64, 2, 1), 512, PJ_SMEM>>>(cur, Wq + l * 65536, bq + l * 256,
                                                   qq, KB * KTQ, 0, 0,
                                                   nullptr, nullptr, nullptr, 1 << 30);
        float* wsl = out_ws + (long long)l * KB * KH * KTQ * KS;
        scores_mma_kernel<<<dim3(32, 8, 16), 256, SC_SMEM>>>(
            qq, kk + l * 262144, pp + l * 524032,
            pbu + l * 256, pbv + l * 256, ews, gstats);
        av_fused<<<dim3(32, 16), 256, AV_SMEM>>>(ews, wsl, vv + l * 262144, gstats, ao);
        float* nxt = (l == KL - 1) ? out : xx;
        proj_mma<<<dim3(64, 2, 1), 512, PJ_SMEM>>>(ao, Wo + l * 65536, bo + l * 256,
                                                   nxt, KB * KTQ, 0, 0,
                                                   nullptr, nullptr, nullptr, 1 << 30);
        cur = nxt;
    }
}

// round 13
// speedup vs baseline: 1.4915x; 1.2023x over previous
#include <cuda_runtime.h>
#include <cuda_fp16.h>
#include <math.h>
#include <stdint.h>

#define KB   2
#define KTQ  4096
#define KS   1024
#define KD   256
#define KH   8
#define KL   4
#define KP   2047
#define XE   (KB*KTQ*KD)

__device__ float g_scratch[12057344];
__device__ __half g_ews[67108864];

// ===================== mma.sync helpers ========================
__device__ __forceinline__ void mma_tf32(float* c, const uint32_t* a, const uint32_t* b) {
    asm volatile("mma.sync.aligned.m16n8k8.row.col.f32.tf32.tf32.f32 "
        "{%0,%1,%2,%3}, {%4,%5,%6,%7}, {%8,%9}, {%0,%1,%2,%3};\n"
        : "+f"(c[0]), "+f"(c[1]), "+f"(c[2]), "+f"(c[3])
        : "r"(a[0]), "r"(a[1]), "r"(a[2]), "r"(a[3]), "r"(b[0]), "r"(b[1]));
}
__device__ __forceinline__ void mma_f16(float* c, const uint32_t* a, const uint32_t* b) {
    asm volatile("mma.sync.aligned.m16n8k16.row.col.f32.f16.f16.f32 "
        "{%0,%1,%2,%3}, {%4,%5,%6,%7}, {%8,%9}, {%0,%1,%2,%3};\n"
        : "+f"(c[0]), "+f"(c[1]), "+f"(c[2]), "+f"(c[3])
        : "r"(a[0]), "r"(a[1]), "r"(a[2]), "r"(a[3]), "r"(b[0]), "r"(b[1]));
}
__device__ __forceinline__ float cvt_tf32(float x) {
    float y;
    asm("cvt.rna.tf32.f32 %0, %1;" : "=f"(y) : "f"(x));
    return y;
}
__device__ __forceinline__ float4 cvt_tf32x4(float4 v) {
    v.x = cvt_tf32(v.x); v.y = cvt_tf32(v.y);
    v.z = cvt_tf32(v.z); v.w = cvt_tf32(v.w);
    return v;
}
__device__ __forceinline__ uint2 f4_to_h4(float4 v) {
    __half2 h01 = __floats2half2_rn(v.x, v.y);
    __half2 h23 = __floats2half2_rn(v.z, v.w);
    uint2 u;
    u.x = *reinterpret_cast<uint32_t*>(&h01);
    u.y = *reinterpret_cast<uint32_t*>(&h23);
    return u;
}

// ============================ pe =================================
__global__ void pe_kernel(float* __restrict__ pe) {
    int i = blockIdx.x;
    int j = threadIdx.x;
    double div = exp(-(double)j * 9.210340371976184 / 128.0);
    double a = (1023.0 - (double)i) * div;
    pe[i * KD + 2 * j]     = (float)sin(a);
    pe[i * KD + 2 * j + 1] = (float)cos(a);
}

// ================= proj via 3xTF32 mma, 512 threads =========================
#define PJSTR 36
#define PJ_AB 0
#define PJ_AS 4608
#define PJ_WB 9216
#define PJ_WS 13824
#define PJ_SMEM (18432 * 4)

__global__ __launch_bounds__(512) void proj_mma(
    const float* __restrict__ A, const float* __restrict__ W,
    const float* __restrict__ bias, float* __restrict__ C,
    int M, int wStride, int cStride,
    const float* __restrict__ W2, const float* __restrict__ bias2,
    float* __restrict__ C2, int zSplit)
{
    extern __shared__ float sp[];
    int m0 = blockIdx.x * 128, n0 = blockIdx.y * 128;
    int z = blockIdx.z;
    if (z >= zSplit) { W = W2; bias = bias2; C = C2; z -= zSplit; }
    W += (long long)z * wStride;
    C += (long long)z * cStride;
    if (bias) bias += z * 256;
    int tid = threadIdx.x;
    int wid = tid >> 5, lane = tid & 31;
    int wy = wid >> 2, wx = wid & 3;
    int g = lane >> 2, t = lane & 3;
    float acc[2][4][4] = {};

    for (int k0 = 0; k0 < 256; k0 += 32) {
        #pragma unroll
        for (int it = 0; it < 2; it++) {
            int e = tid + 512 * it;
            int r = e >> 3, f = e & 7;
            int row = m0 + r;
            float4 a4 = (row < M) ? *(const float4*)&A[(long long)row * 256 + k0 + f * 4]
                                  : make_float4(0.f, 0.f, 0.f, 0.f);
            float4 ab = cvt_tf32x4(a4);
            float4 as = make_float4(a4.x - ab.x, a4.y - ab.y, a4.z - ab.z, a4.w - ab.w);
            *(float4*)&sp[PJ_AB + r * PJSTR + f * 4] = ab;
            *(float4*)&sp[PJ_AS + r * PJSTR + f * 4] = cvt_tf32x4(as);
            float4 w4 = *(const float4*)&W[(long long)(n0 + r) * 256 + k0 + f * 4];
            float4 wb = cvt_tf32x4(w4);
            float4 ws4 = make_float4(w4.x - wb.x, w4.y - wb.y, w4.z - wb.z, w4.w - wb.w);
            *(float4*)&sp[PJ_WB + r * PJSTR + f * 4] = wb;
            *(float4*)&sp[PJ_WS + r * PJSTR + f * 4] = cvt_tf32x4(ws4);
        }
        __syncthreads();
        #pragma unroll
        for (int k0i = 0; k0i < 4; k0i++) {
            int kk = k0i * 8;
            uint32_t aB[2][4], aS[2][4], bB[4][2], bS[4][2];
            #pragma unroll
            for (int mi = 0; mi < 2; mi++) {
                int r0 = wy * 32 + mi * 16;
                aB[mi][0] = __float_as_uint(sp[PJ_AB + (r0 + g) * PJSTR + kk + t]);
                aB[mi][1] = __float_as_uint(sp[PJ_AB + (r0 + g + 8) * PJSTR + kk + t]);
                aB[mi][2] = __float_as_uint(sp[PJ_AB + (r0 + g) * PJSTR + kk + t + 4]);
                aB[mi][3] = __float_as_uint(sp[PJ_AB + (r0 + g + 8) * PJSTR + kk + t + 4]);
                aS[mi][0] = __float_as_uint(sp[PJ_AS + (r0 + g) * PJSTR + kk + t]);
                aS[mi][1] = __float_as_uint(sp[PJ_AS + (r0 + g + 8) * PJSTR + kk + t]);
                aS[mi][2] = __float_as_uint(sp[PJ_AS + (r0 + g) * PJSTR + kk + t + 4]);
                aS[mi][3] = __float_as_uint(sp[PJ_AS + (r0 + g + 8) * PJSTR + kk + t + 4]);
            }
            #pragma unroll
            for (int ni = 0; ni < 4; ni++) {
                int c0 = wx * 32 + ni * 8;
                bB[ni][0] = __float_as_uint(sp[PJ_WB + (c0 + g) * PJSTR + kk + t]);
                bB[ni][1] = __float_as_uint(sp[PJ_WB + (c0 + g) * PJSTR + kk + t + 4]);
                bS[ni][0] = __float_as_uint(sp[PJ_WS + (c0 + g) * PJSTR + kk + t]);
                bS[ni][1] = __float_as_uint(sp[PJ_WS + (c0 + g) * PJSTR + kk + t + 4]);
            }
            #pragma unroll
            for (int mi = 0; mi < 2; mi++)
                #pragma unroll
                for (int ni = 0; ni < 4; ni++) {
                    mma_tf32(acc[mi][ni], aB[mi], bS[ni]);
                    mma_tf32(acc[mi][ni], aS[mi], bB[ni]);
                    mma_tf32(acc[mi][ni], aB[mi], bB[ni]);
                }
        }
        __syncthreads();
    }
    #pragma unroll
    for (int mi = 0; mi < 2; mi++) {
        int r1 = m0 + wy * 32 + mi * 16 + g;
        int r2 = r1 + 8;
        #pragma unroll
        for (int ni = 0; ni < 4; ni++) {
            int cx = wx * 32 + ni * 8 + 2 * t;
            float b0 = bias ? bias[n0 + cx] : 0.f;
            float b1 = bias ? bias[n0 + cx + 1] : 0.f;
            if (r1 < M)
                *(float2*)&C[(long long)r1 * 256 + n0 + cx] =
                    make_float2(acc[mi][ni][0] + b0, acc[mi][ni][1] + b1);
            if (r2 < M)
                *(float2*)&C[(long long)r2 * 256 + n0 + cx] =
                    make_float2(acc[mi][ni][2] + b0, acc[mi][ni][3] + b1);
        }
    }
}

// ============ scores: fp16 m16n8k16 MMA, banded G, fp16 ews out =============
#define HSTR 40
#define QUH_O 0
#define KTH_O 5120
#define QVH_O 10240
#define PDH_O 15400
// float-indexed region (after 51280B of halves, 16B aligned)
#define G_O   12832
#define GSTR  260
#define SMAX_O (G_O + 128 * GSTR)
#define SSUM_O (SMAX_O + 512)
#define SC_FLOATS (SSUM_O + 512)
#define SC_SMEM (SC_FLOATS * 4)

__global__ __launch_bounds__(256, 1) void scores_mma_kernel(
    const float* __restrict__ q, const float* __restrict__ kmat,
    const float* __restrict__ p, const float* __restrict__ pbu,
    const float* __restrict__ pbv, __half* __restrict__ ews,
    float2* __restrict__ gstats)
{
    extern __shared__ float sm[];
    __half* smh = (__half*)sm;
    int q0 = blockIdx.x * 128, m0 = blockIdx.y * 128;
    int bh = blockIdx.z;
    int b = bh >> 3, h = bh & 7;
    int tid = threadIdx.x;
    int wid = tid >> 5, lane = tid & 31;
    int wy = wid >> 2, wx = wid & 3;
    int g = lane >> 2, t = lane & 3;

    int dlo = m0 - q0 + 3969;
    int da  = dlo >> 11;
    bool boundary = ((dlo >> 11) != ((dlo + 254) >> 11));

    const float* qb = q + (long long)b * KTQ * 256 + h * 32;
    #pragma unroll
    for (int it = 0; it < 4; it++) {
        int e = tid + 256 * it;
        int r = e >> 3, fj = e & 7;
        float4 bu4 = *(const float4*)&pbu[h * 32 + fj * 4];
        float4 a = *(const float4*)&qb[(long long)(q0 + r) * 256 + fj * 4];
        a.x += bu4.x; a.y += bu4.y; a.z += bu4.z; a.w += bu4.w;
        *(uint2*)&smh[QUH_O + r * HSTR + fj * 4] = f4_to_h4(a);
        float4 kk4 = *(const float4*)&kmat[(long long)(m0 + r) * 256 + h * 32 + fj * 4];
        *(uint2*)&smh[KTH_O + r * HSTR + fj * 4] = f4_to_h4(kk4);
    }
    #pragma unroll
    for (int it = 0; it < 5; it++) {
        int e = tid + 256 * it;
        if (e < 129 * 8) {
            int r = e >> 3, fj = e & 7;
            float4 bv4 = *(const float4*)&pbv[h * 32 + fj * 4];
            int rv = q0 + da + r; if (rv > KTQ - 1) rv = KTQ - 1;
            float4 v = *(const float4*)&qb[(long long)rv * 256 + fj * 4];
            v.x += bv4.x; v.y += bv4.y; v.z += bv4.z; v.w += bv4.w;
            *(uint2*)&smh[QVH_O + r * HSTR + fj * 4] = f4_to_h4(v);
        }
    }
    #pragma unroll
    for (int it = 0; it < 8; it++) {
        int e = tid + 256 * it;
        int r = e >> 3, fj = e & 7;
        int d = dlo + r;
        int cm = d & 2047;
        float4 v = make_float4(0.f, 0.f, 0.f, 0.f);
        if (cm > 0 && r < 255)
            v = *(const float4*)&p[(long long)(cm - 1) * 256 + h * 32 + fj * 4];
        *(uint2*)&smh[PDH_O + r * HSTR + fj * 4] = f4_to_h4(v);
    }
    __syncthreads();

    // ---- phase 1: banded G[r][ix] = Qv_sh[r] . Pd[ix], fp16 k16 ----
    if (!boundary) {
        int s0b = (wy == 0) ? 64 : 0;
        float accg[4][6][4] = {};
        #pragma unroll
        for (int k0 = 0; k0 < 2; k0++) {
            int kk = k0 * 16;
            uint32_t a[4][4], bb[6][2];
            #pragma unroll
            for (int mi = 0; mi < 4; mi++) {
                int r0 = wy * 64 + mi * 16;
                a[mi][0] = *(const uint32_t*)&smh[QVH_O + (r0 + g) * HSTR + kk + 2 * t];
                a[mi][1] = *(const uint32_t*)&smh[QVH_O + (r0 + g + 8) * HSTR + kk + 2 * t];
                a[mi][2] = *(const uint32_t*)&smh[QVH_O + (r0 + g) * HSTR + kk + 2 * t + 8];
                a[mi][3] = *(const uint32_t*)&smh[QVH_O + (r0 + g + 8) * HSTR + kk + 2 * t + 8];
            }
            #pragma unroll
            for (int ni = 0; ni < 6; ni++) {
                int c0 = s0b + (wx * 6 + ni) * 8;
                bb[ni][0] = *(const uint32_t*)&smh[PDH_O + (c0 + g) * HSTR + kk + 2 * t];
                bb[ni][1] = *(const uint32_t*)&smh[PDH_O + (c0 + g) * HSTR + kk + 2 * t + 8];
            }
            #pragma unroll
            for (int mi = 0; mi < 4; mi++)
                #pragma unroll
                for (int ni = 0; ni < 6; ni++)
                    mma_f16(accg[mi][ni], a[mi], bb[ni]);
        }
        #pragma unroll
        for (int mi = 0; mi < 4; mi++) {
            int r1 = wy * 64 + mi * 16 + g;
            #pragma unroll
            for (int ni = 0; ni < 6; ni++) {
                int cx = s0b + (wx * 6 + ni) * 8 + 2 * t;
                *(float2*)&sm[G_O + r1 * GSTR + cx] =
                    make_float2(accg[mi][ni][0], accg[mi][ni][1]);
                *(float2*)&sm[G_O + (r1 + 8) * GSTR + cx] =
                    make_float2(accg[mi][ni][2], accg[mi][ni][3]);
            }
        }
    } else {
        int trb = (tid >> 4) * 8, tcb = (tid & 15) * 8;
        #pragma unroll
        for (int i = 0; i < 8; i++) {
            int rr = trb + i;
            #pragma unroll
            for (int j = 0; j < 8; j++) {
                int c = tcb + j;
                int ix = c - rr + 127;
                int d = dlo + ix;
                int tt = rr + (d >> 11) - da;
                float s = 0.f;
                #pragma unroll
                for (int k = 0; k < 32; k++)
                    s += __half2float(smh[QVH_O + tt * HSTR + k])
                       * __half2float(smh[PDH_O + ix * HSTR + k]);
                sm[G_O + rr * GSTR + ix] = s;
            }
        }
    }
    __syncthreads();

    // ---- phase 2: ac = Qu . K^T, fp16 k16 ----
    float acc[4][4][4] = {};
    #pragma unroll
    for (int k0 = 0; k0 < 2; k0++) {
        int kk = k0 * 16;
        uint32_t a[4][4], bb[4][2];
        #pragma unroll
        for (int mi = 0; mi < 4; mi++) {
            int r0 = wy * 64 + mi * 16;
            a[mi][0] = *(const uint32_t*)&smh[QUH_O + (r0 + g) * HSTR + kk + 2 * t];
            a[mi][1] = *(const uint32_t*)&smh[QUH_O + (r0 + g + 8) * HSTR + kk + 2 * t];
            a[mi][2] = *(const uint32_t*)&smh[QUH_O + (r0 + g) * HSTR + kk + 2 * t + 8];
            a[mi][3] = *(const uint32_t*)&smh[QUH_O + (r0 + g + 8) * HSTR + kk + 2 * t + 8];
        }
        #pragma unroll
        for (int ni = 0; ni < 4; ni++) {
            int c0 = wx * 32 + ni * 8;
            bb[ni][0] = *(const uint32_t*)&smh[KTH_O + (c0 + g) * HSTR + kk + 2 * t];
            bb[ni][1] = *(const uint32_t*)&smh[KTH_O + (c0 + g) * HSTR + kk + 2 * t + 8];
        }
        #pragma unroll
        for (int mi = 0; mi < 4; mi++)
            #pragma unroll
            for (int ni = 0; ni < 4; ni++)
                mma_f16(acc[mi][ni], a[mi], bb[ni]);
    }

    // ---- combine with bd, scale ----
    const float sc = 0.17677669529663687f;
    #pragma unroll
    for (int mi = 0; mi < 4; mi++) {
        int r1 = wy * 64 + mi * 16 + g;
        int r2 = r1 + 8;
        #pragma unroll
        for (int ni = 0; ni < 4; ni++) {
            int cx = wx * 32 + ni * 8 + 2 * t;
            acc[mi][ni][0] = (acc[mi][ni][0] + sm[G_O + r1 * GSTR + cx     - r1 + 127]) * sc;
            acc[mi][ni][1] = (acc[mi][ni][1] + sm[G_O + r1 * GSTR + cx + 1 - r1 + 127]) * sc;
            acc[mi][ni][2] = (acc[mi][ni][2] + sm[G_O + r2 * GSTR + cx     - r2 + 127]) * sc;
            acc[mi][ni][3] = (acc[mi][ni][3] + sm[G_O + r2 * GSTR + cx + 1 - r2 + 127]) * sc;
        }
    }

    // ---- row-tile max reduce ----
    __syncthreads();
    float rm1[4], rm2[4];
    #pragma unroll
    for (int mi = 0; mi < 4; mi++) {
        int lr1 = wy * 64 + mi * 16 + g;
        int lr2 = lr1 + 8;
        float mx1 = -1e30f, mx2 = -1e30f;
        #pragma unroll
        for (int ni = 0; ni < 4; ni++) {
            mx1 = fmaxf(mx1, fmaxf(acc[mi][ni][0], acc[mi][ni][1]));
            mx2 = fmaxf(mx2, fmaxf(acc[mi][ni][2], acc[mi][ni][3]));
        }
        mx1 = fmaxf(mx1, __shfl_xor_sync(0xffffffffu, mx1, 1));
        mx1 = fmaxf(mx1, __shfl_xor_sync(0xffffffffu, mx1, 2));
        mx2 = fmaxf(mx2, __shfl_xor_sync(0xffffffffu, mx2, 1));
        mx2 = fmaxf(mx2, __shfl_xor_sync(0xffffffffu, mx2, 2));
        if (t == 0) {
            sm[SMAX_O + lr1 * 4 + wx] = mx1;
            sm[SMAX_O + lr2 * 4 + wx] = mx2;
        }
    }
    __syncthreads();

    // ---- exp + store fp16 + sum reduce ----
    #pragma unroll
    for (int mi = 0; mi < 4; mi++) {
        int lr1 = wy * 64 + mi * 16 + g;
        int lr2 = lr1 + 8;
        float a1 = fmaxf(fmaxf(sm[SMAX_O + lr1 * 4], sm[SMAX_O + lr1 * 4 + 1]),
                         fmaxf(sm[SMAX_O + lr1 * 4 + 2], sm[SMAX_O + lr1 * 4 + 3]));
        float a2 = fmaxf(fmaxf(sm[SMAX_O + lr2 * 4], sm[SMAX_O + lr2 * 4 + 1]),
                         fmaxf(sm[SMAX_O + lr2 * 4 + 2], sm[SMAX_O + lr2 * 4 + 3]));
        rm1[mi] = a1; rm2[mi] = a2;
        long long grow1 = ((long long)bh * KTQ + q0 + lr1) * KS + m0;
        long long grow2 = grow1 + 8 * KS;
        float s1 = 0.f, s2 = 0.f;
        #pragma unroll
        for (int ni = 0; ni < 4; ni++) {
            int cx = wx * 32 + ni * 8 + 2 * t;
            float e0 = __expf(acc[mi][ni][0] - a1);
            float e1 = __expf(acc[mi][ni][1] - a1);
            float e2 = __expf(acc[mi][ni][2] - a2);
            float e3 = __expf(acc[mi][ni][3] - a2);
            s1 += e0 + e1;
            s2 += e2 + e3;
            *(__half2*)&ews[grow1 + cx] = __floats2half2_rn(e0, e1);
            *(__half2*)&ews[grow2 + cx] = __floats2half2_rn(e2, e3);
        }
        s1 += __shfl_xor_sync(0xffffffffu, s1, 1);
        s1 += __shfl_xor_sync(0xffffffffu, s1, 2);
        s2 += __shfl_xor_sync(0xffffffffu, s2, 1);
        s2 += __shfl_xor_sync(0xffffffffu, s2, 2);
        if (t == 0) {
            sm[SSUM_O + lr1 * 4 + wx] = s1;
            sm[SSUM_O + lr2 * 4 + wx] = s2;
        }
    }
    __syncthreads();
    if (wx == 0 && t == 0) {
        int my = m0 >> 7;
        long long sb = ((long long)bh * 8 + my) * KTQ + q0;
        #pragma unroll
        for (int mi = 0; mi < 4; mi++) {
            int lr1 = wy * 64 + mi * 16 + g;
            int lr2 = lr1 + 8;
            float s1 = sm[SSUM_O + lr1 * 4] + sm[SSUM_O + lr1 * 4 + 1]
                     + sm[SSUM_O + lr1 * 4 + 2] + sm[SSUM_O + lr1 * 4 + 3];
            float s2 = sm[SSUM_O + lr2 * 4] + sm[SSUM_O + lr2 * 4 + 1]
                     + sm[SSUM_O + lr2 * 4 + 2] + sm[SSUM_O + lr2 * 4 + 3];
            gstats[sb + lr1] = make_float2(rm1[mi], s1);
            gstats[sb + lr2] = make_float2(rm2[mi], s2);
        }
    }
}

// ===== av: raw fp16 e as A operand, fp16 V as B, fac folded in epilogue =====
#define AHSTR 72
#define AVH_A 0
#define AVH_V (128 * AHSTR)
// float region after (128+32)*72 halves = 11520 halves = 23040 B -> float idx 5760
#define AV_M 5760
#define AV_I 5888
#define AV_S 6016
#define AV_F 8064
#define AV_SMEM ((8064 + 1024) * 4)

__global__ __launch_bounds__(256) void av_fused(
    const __half* __restrict__ ews, float* __restrict__ ws,
    const float* __restrict__ vmat,
    const float2* __restrict__ gstats, float* __restrict__ ao)
{
    extern __shared__ float sv[];
    __half* svh = (__half*)sv;
    float2* sSt = (float2*)(sv + AV_S);
    int q0 = blockIdx.x * 128;
    int bh = blockIdx.y;
    int b = bh >> 3, h = bh & 7;
    int tid = threadIdx.x;
    int wid = tid >> 5, lane = tid & 31;
    int g = lane >> 2, t = lane & 3;

    for (int idx = tid; idx < 1024; idx += 256)
        sSt[idx] = gstats[(((long long)bh * 8 + (idx >> 7)) << 12) + q0 + (idx & 127)];
    __syncthreads();
    if (tid < 128) {
        float M = -1e30f;
        #pragma unroll
        for (int mt = 0; mt < 8; mt++) M = fmaxf(M, sSt[mt * 128 + tid].x);
        float s = 0.f;
        #pragma unroll
        for (int mt = 0; mt < 8; mt++)
            s += sSt[mt * 128 + tid].y * __expf(sSt[mt * 128 + tid].x - M);
        sv[AV_M + tid] = M;
        sv[AV_I + tid] = 1.f / s;
    }
    __syncthreads();
    for (int idx = tid; idx < 1024; idx += 256) {
        int r = idx & 127;
        sv[AV_F + idx] = __expf(sSt[idx].x - sv[AV_M + r]) * sv[AV_I + r];
    }
    __syncthreads();

    const __half* ewsrow = ews + ((long long)bh * KTQ + q0) * KS;
    float* wsrow = ws + ((long long)bh * KTQ + q0) * KS;
    float acc[4][4] = {};

    for (int s0 = 0; s0 < KS; s0 += 64) {
        int mt = s0 >> 7;
        // stage raw e halves + write normalized fp32 ws
        #pragma unroll
        for (int it = 0; it < 4; it++) {
            int e = tid + 256 * it;
            int r = e >> 3, f = e & 7;
            long long off = (long long)r * KS + s0 + f * 8;
            uint4 rh = *(const uint4*)&ewsrow[off];
            *(uint4*)&svh[AVH_A + r * AHSTR + f * 8] = rh;
            float fac = sv[AV_F + mt * 128 + r];
            float2 p0 = __half22float2(*reinterpret_cast<__half2*>(&rh.x));
            float2 p1 = __half22float2(*reinterpret_cast<__half2*>(&rh.y));
            float2 p2 = __half22float2(*reinterpret_cast<__half2*>(&rh.z));
            float2 p3 = __half22float2(*reinterpret_cast<__half2*>(&rh.w));
            float4 o0 = make_float4(p0.x * fac, p0.y * fac, p1.x * fac, p1.y * fac);
            float4 o1 = make_float4(p2.x * fac, p2.y * fac, p3.x * fac, p3.y * fac);
            *(float4*)&wsrow[off]     = o0;
            *(float4*)&wsrow[off + 4] = o1;
        }
        // stage V chunk as fp16 [n][k]
        #pragma unroll
        for (int it = 0; it < 8; it++) {
            int e = tid + 256 * it;
            int k = e >> 5, n = e & 31;
            svh[AVH_V + n * AHSTR + k] =
                __float2half_rn(vmat[(long long)(s0 + k) * 256 + h * 32 + n]);
        }
        __syncthreads();

        int r0 = wid * 16;
        float accC[4][4] = {};
        #pragma unroll
        for (int k0 = 0; k0 < 4; k0++) {
            int kk = k0 * 16;
            uint32_t a[4];
            a[0] = *(const uint32_t*)&svh[AVH_A + (r0 + g) * AHSTR + kk + 2 * t];
            a[1] = *(const uint32_t*)&svh[AVH_A + (r0 + g + 8) * AHSTR + kk + 2 * t];
            a[2] = *(const uint32_t*)&svh[AVH_A + (r0 + g) * AHSTR + kk + 2 * t + 8];
            a[3] = *(const uint32_t*)&svh[AVH_A + (r0 + g + 8) * AHSTR + kk + 2 * t + 8];
            #pragma unroll
            for (int ni = 0; ni < 4; ni++) {
                uint32_t bb[2];
                bb[0] = *(const uint32_t*)&svh[AVH_V + (ni * 8 + g) * AHSTR + kk + 2 * t];
                bb[1] = *(const uint32_t*)&svh[AVH_V + (ni * 8 + g) * AHSTR + kk + 2 * t + 8];
                mma_f16(accC[ni], a, bb);
            }
        }
        float facA = sv[AV_F + mt * 128 + r0 + g];
        float facB = sv[AV_F + mt * 128 + r0 + g + 8];
        #pragma unroll
        for (int ni = 0; ni < 4; ni++) {
            acc[ni][0] += facA * accC[ni][0];
            acc[ni][1] += facA * accC[ni][1];
            acc[ni][2] += facB * accC[ni][2];
            acc[ni][3] += facB * accC[ni][3];
        }
        __syncthreads();
    }
    int r1 = q0 + wid * 16 + g;
    float* aob = ao + ((long long)b * KTQ + r1) * 256 + h * 32;
    #pragma unroll
    for (int ni = 0; ni < 4; ni++) {
        int cx = ni * 8 + 2 * t;
        *(float2*)&aob[cx]           = make_float2(acc[ni][0], acc[ni][1]);
        *(float2*)&aob[8 * 256 + cx] = make_float2(acc[ni][2], acc[ni][3]);
    }
}

// ---------------------------------------------------------------------------
extern "C" void kernel_launch(void* const* d_in, const int* in_sizes, int n_in,
                              void* d_out, int out_size)
{
    const float* vis  = (const float*)d_in[0];
    const float* mem  = (const float*)d_in[1];
    const float* Wq   = (const float*)d_in[3];
    const float* bq   = (const float*)d_in[4];
    const float* Wk   = (const float*)d_in[5];
    const float* bk   = (const float*)d_in[6];
    const float* Wv   = (const float*)d_in[7];
    const float* bv   = (const float*)d_in[8];
    const float* Wo   = (const float*)d_in[9];
    const float* bo   = (const float*)d_in[10];
    const float* Wpos = (const float*)d_in[11];
    const float* pbu  = (const float*)d_in[12];
    const float* pbv  = (const float*)d_in[13];

    float* out    = (float*)d_out;
    float* out_ws = out + XE;

    float* scratch = nullptr;
    cudaGetSymbolAddress((void**)&scratch, g_scratch);
    __half* ews = nullptr;
    cudaGetSymbolAddress((void**)&ews, g_ews);
    float* pe = scratch;
    float* pp = pe + 524032;
    float* kk = pp + 4 * 524032;
    float* vv = kk + 4 * 262144;
    float* qq = vv + 4 * 262144;
    float* xx = qq + XE;
    float* ao = xx + XE;
    float2* gstats = (float2*)(ao + XE);

    cudaFuncSetAttribute(scores_mma_kernel,
        cudaFuncAttributeMaxDynamicSharedMemorySize, SC_SMEM);
    cudaFuncSetAttribute(proj_mma,
        cudaFuncAttributeMaxDynamicSharedMemorySize, PJ_SMEM);
    cudaFuncSetAttribute(av_fused,
        cudaFuncAttributeMaxDynamicSharedMemorySize, AV_SMEM);

    pe_kernel<<<KP, 128>>>(pe);

    proj_mma<<<dim3(8, 2, 2 * KL), 512, PJ_SMEM>>>(mem, Wk, bk, kk, KS, 65536, 262144,
                                                   Wv, bv, vv, KL);
    proj_mma<<<dim3(16, 2, KL), 512, PJ_SMEM>>>(pe, Wpos, nullptr, pp, KP, 65536, 524032,
                                                nullptr, nullptr, nullptr, 1 << 30);

    const float* cur = vis;
    for (int l = 0; l < KL; l++) {
        proj_mma<<<dim3(64, 2, 1), 512, PJ_SMEM>>>(cur, Wq + l * 65536, bq + l * 256,
                                                   qq, KB * KTQ, 0, 0,
                                                   nullptr, nullptr, nullptr, 1 << 30);
        float* wsl = out_ws + (long long)l * KB * KH * KTQ * KS;
        scores_mma_kernel<<<dim3(32, 8, 16), 256, SC_SMEM>>>(
            qq, kk + l * 262144, pp + l * 524032,
            pbu + l * 256, pbv + l * 256, ews, gstats);
        av_fused<<<dim3(32, 16), 256, AV_SMEM>>>(ews, wsl, vv + l * 262144, gstats, ao);
        float* nxt = (l == KL - 1) ? out : xx;
        proj_mma<<<dim3(64, 2, 1), 512, PJ_SMEM>>>(ao, Wo + l * 65536, bo + l * 256,
                                                   nxt, KB * KTQ, 0, 0,
                                                   nullptr, nullptr, nullptr, 1 << 30);
        cur = nxt;
    }
}